// round 11
// baseline (speedup 1.0000x reference)
#include <cuda_runtime.h>
#include <cuda_bf16.h>
#include <cstdint>

// ---------------------------------------------------------------------------
// Instant-NGP MLP via mma.sync m16n8k16 BF16, split-bf16 (3-term).
// Round 11: warp tile 32 rows x 32 cols (weight duplication 8x -> 4x),
// hi/lo weight fragments fused in one uint4 (LDS.128), A-operands via
// k-pair-reordered LDS.64. Grid y-pair repack (round 10) retained.
// ---------------------------------------------------------------------------

#define NPTS    2097152
#define NTILES  (NPTS / 128)     // 16384
#define TPB     512
#define NCTA    148
#define GS      513
#define GC      (GS * GS)

// SMEM map in u32 units
#define U_W1F   0                 // uint4[1024]  = 4096 u32
#define U_W2F   4096              // uint4[4096]  = 16384 u32
#define U_FEATH 20480             // 128*24 = 3072
#define U_FEATL 23552             // 3072
#define U_H1H   26624             // 128*72 = 9216
#define U_H1L   35840             // 9216
#define F_B1    45056             // 128
#define F_B2    45184             // 128
#define F_W3    45312             // 128
#define F_B3    45440             // 4
#define F_PART  45444             // 128*5 = 640
#define SM_U32  46084
#define SMEM_BYTES (SM_U32 * 4)   // 184336 B

// y-pair packed grid: P[l][i][j] = (g[i][j].xy, g[i][j+1].xy)
__device__ float4 g_pack[16 * GC];

__device__ constexpr int kResTab[16] = {16, 20, 25, 32, 40, 50, 64, 80,
                                        101, 128, 161, 203, 256, 322, 406, 512};

__device__ __forceinline__ float bf16f(float v) {
    return __bfloat162float(__float2bfloat16_rn(v));
}
__device__ __forceinline__ uint32_t packbf(float e0, float e1) {
    __nv_bfloat162 t = __halves2bfloat162(__float2bfloat16_rn(e0),
                                          __float2bfloat16_rn(e1));
    return *reinterpret_cast<uint32_t*>(&t);
}

__device__ __forceinline__ void mmab(float* d, const uint32_t* a,
                                     uint32_t b0, uint32_t b1) {
    asm volatile(
        "mma.sync.aligned.m16n8k16.row.col.f32.bf16.bf16.f32 "
        "{%0,%1,%2,%3}, {%4,%5,%6,%7}, {%8,%9}, {%0,%1,%2,%3};"
        : "+f"(d[0]), "+f"(d[1]), "+f"(d[2]), "+f"(d[3])
        : "r"(a[0]), "r"(a[1]), "r"(a[2]), "r"(a[3]), "r"(b0), "r"(b1));
}

// grid repack: 2 float2 reads -> 1 aligned float4 (y-pair)
__global__ __launch_bounds__(256)
void repack_kernel(const float* __restrict__ grids) {
    int idx = blockIdx.x * 256 + threadIdx.x;
    if (idx >= 16 * GC) return;
    int j = idx % GS;
    int i = (idx / GS) % GS;
    int l = idx / GC;
    const float2* g = reinterpret_cast<const float2*>(grids) + (size_t)l * GC;
    float2 a = __ldg(g + i * GS + j);
    float2 b = __ldg(g + i * GS + min(j + 1, GS - 1));
    g_pack[idx] = make_float4(a.x, a.y, b.x, b.y);
}

// 4-level gather via packed grid: 2 LDG.128 per level
template <int L0>
__device__ __forceinline__ void gather4(float2 xy, float* f) {
    #pragma unroll
    for (int i = 0; i < 4; i++) {
        const int   ri = kResTab[L0 + i];
        const float rf = (float)ri;
        const float fx = xy.x * rf, fy = xy.y * rf;
        const float fxf = floorf(fx), fyf = floorf(fy);
        const float wx = fx - fxf, wy = fy - fyf;
        int ix0 = min(max((int)fxf, 0), ri);
        int iy0 = min(max((int)fyf, 0), ri);
        int ix1 = min(ix0 + 1, ri);
        const float4* P = g_pack + (size_t)(L0 + i) * GC;
        const float4 a = __ldg(P + ix0 * GS + iy0);
        const float4 b = __ldg(P + ix1 * GS + iy0);
        const float owx = 1.0f - wx, owy = 1.0f - wy;
        const float t00 = a.x * owx + b.x * wx;
        const float t01 = a.y * owx + b.y * wx;
        const float t10 = a.z * owx + b.z * wx;
        const float t11 = a.w * owx + b.w * wx;
        f[2 * i + 0] = t00 * owy + t10 * wy;
        f[2 * i + 1] = t01 * owy + t11 * wy;
    }
}

__global__ __launch_bounds__(TPB, 1)
void Model_61065845014888_kernel(
    const float* __restrict__ x,
    const float* __restrict__ W1, const float* __restrict__ b1,
    const float* __restrict__ W2, const float* __restrict__ b2,
    const float* __restrict__ W3, const float* __restrict__ b3,
    float* __restrict__ out)
{
    extern __shared__ float sm[];
    uint32_t* smu = reinterpret_cast<uint32_t*>(sm);
    uint4*    sm4 = reinterpret_cast<uint4*>(sm);
    const int tid = threadIdx.x;

    // ---- stage weights: fused hi/lo uint4 fragments, once ----
    // uint4 idx: ln = idx&31, g = (idx>>5)&15, s = idx>>9
    // reg r pair: k = s*16 + 2*(ln&3) + 8r (+0,+1), j = g*8 + (ln>>2)
    for (int idx = tid; idx < 1024; idx += TPB) {
        int ln = idx & 31, g = (idx >> 5) & 15, s = idx >> 9;
        int k0 = s * 16 + 2 * (ln & 3), k1 = k0 + 8;
        int j = g * 8 + (ln >> 2);
        float w00 = W1[k0 * 128 + j], w01 = W1[(k0 + 1) * 128 + j];
        float w10 = W1[k1 * 128 + j], w11 = W1[(k1 + 1) * 128 + j];
        float h00 = bf16f(w00), h01 = bf16f(w01);
        float h10 = bf16f(w10), h11 = bf16f(w11);
        sm4[U_W1F / 4 + idx] = make_uint4(
            packbf(h00, h01), packbf(h10, h11),
            packbf(w00 - h00, w01 - h01), packbf(w10 - h10, w11 - h11));
    }
    for (int idx = tid; idx < 4096; idx += TPB) {
        int ln = idx & 31, g = (idx >> 5) & 15, s = idx >> 9;
        int k0 = s * 16 + 2 * (ln & 3), k1 = k0 + 8;
        int j = g * 8 + (ln >> 2);
        float w00 = W2[k0 * 128 + j], w01 = W2[(k0 + 1) * 128 + j];
        float w10 = W2[k1 * 128 + j], w11 = W2[(k1 + 1) * 128 + j];
        float h00 = bf16f(w00), h01 = bf16f(w01);
        float h10 = bf16f(w10), h11 = bf16f(w11);
        sm4[U_W2F / 4 + idx] = make_uint4(
            packbf(h00, h01), packbf(h10, h11),
            packbf(w00 - h00, w01 - h01), packbf(w10 - h10, w11 - h11));
    }
    if (tid < 128) {
        sm[F_B1 + tid] = b1[tid];
        sm[F_B2 + tid] = b2[tid];
        sm[F_W3 + tid] = W3[tid];
    }
    if (tid == 0) sm[F_B3] = b3[0];

    // warp tile: 32 rows x 32 cols
    const int wid  = tid >> 5;
    const int lane = tid & 31;
    const int rg   = wid & 3;          // row group (32 rows)
    const int ch   = wid >> 2;         // col quarter (32 cols)
    const int tg   = lane & 3;
    const int gid  = lane >> 2;
    const int arow = rg * 32 + gid;
    const int jw   = ch * 32;

    const int gpt = tid >> 2;
    const int gq  = tid & 3;

    __syncthreads();

    for (int t = blockIdx.x; t < NTILES; t += NCTA) {
        // ============ gather -> split bf16 feat (k-pair reordered) ========
        {
            const int p = t * 128 + gpt;
            const float2 xy = __ldg(reinterpret_cast<const float2*>(x) + p);
            float f[8];
            switch (gq) {
                case 0: gather4<0>(xy, f);  break;
                case 1: gather4<4>(xy, f);  break;
                case 2: gather4<8>(xy, f);  break;
                default: gather4<12>(xy, f); break;
            }
            const int cb = U_FEATH + gpt * 24 + (gq >> 1) * 8 + (gq & 1);
            #pragma unroll
            for (int i = 0; i < 4; i++) {
                float h0 = bf16f(f[2*i]), h1 = bf16f(f[2*i+1]);
                smu[cb + 2 * i]                       = packbf(h0, h1);
                smu[cb + 2 * i + (U_FEATL - U_FEATH)] =
                    packbf(f[2*i] - h0, f[2*i+1] - h1);
            }
        }
        __syncthreads();

        float d[4][2][4];

        // ============ GEMM1: D1 = feat @ W1 + b1 (2 k16-steps) ============
        #pragma unroll
        for (int f = 0; f < 4; f++) {
            const float2 bv = *reinterpret_cast<const float2*>(
                sm + F_B1 + jw + f * 8 + tg * 2);
            #pragma unroll
            for (int mi = 0; mi < 2; mi++) {
                d[f][mi][0] = bv.x; d[f][mi][1] = bv.y;
                d[f][mi][2] = bv.x; d[f][mi][3] = bv.y;
            }
        }
        #pragma unroll
        for (int s = 0; s < 2; s++) {
            const int ab = s * 8 + 2 * tg;
            uint32_t ah[2][4], al[2][4];
            #pragma unroll
            for (int mi = 0; mi < 2; mi++) {
                const int r0 = (arow + 16 * mi) * 24 + ab;
                const int r1 = r0 + 8 * 24;
                uint2 v0 = *reinterpret_cast<const uint2*>(smu + U_FEATH + r0);
                uint2 v1 = *reinterpret_cast<const uint2*>(smu + U_FEATH + r1);
                uint2 u0 = *reinterpret_cast<const uint2*>(smu + U_FEATL + r0);
                uint2 u1 = *reinterpret_cast<const uint2*>(smu + U_FEATL + r1);
                ah[mi][0] = v0.x; ah[mi][1] = v1.x; ah[mi][2] = v0.y; ah[mi][3] = v1.y;
                al[mi][0] = u0.x; al[mi][1] = u1.x; al[mi][2] = u0.y; al[mi][3] = u1.y;
            }
            const int fb = U_W1F / 4 + (s * 16 + ch * 4) * 32 + lane;
            #pragma unroll
            for (int f = 0; f < 4; f++) {
                const uint4 w = sm4[fb + f * 32];
                #pragma unroll
                for (int mi = 0; mi < 2; mi++) {
                    mmab(d[f][mi], ah[mi], w.x, w.y);
                    mmab(d[f][mi], al[mi], w.x, w.y);
                    mmab(d[f][mi], ah[mi], w.z, w.w);
                }
            }
        }

        // relu + split-store h1 (k-pair reordered, stride 72)
        #pragma unroll
        for (int f = 0; f < 4; f++) {
            const int cp = (ch * 2 + (f >> 1)) * 8 + 2 * tg + (f & 1);
            #pragma unroll
            for (int mi = 0; mi < 2; mi++) {
                const int r0 = arow + 16 * mi, r1 = r0 + 8;
                float v0 = fmaxf(d[f][mi][0], 0.0f), v1 = fmaxf(d[f][mi][1], 0.0f);
                float v2 = fmaxf(d[f][mi][2], 0.0f), v3 = fmaxf(d[f][mi][3], 0.0f);
                float h0 = bf16f(v0), h1 = bf16f(v1);
                float h2 = bf16f(v2), h3 = bf16f(v3);
                smu[U_H1H + r0 * 72 + cp] = packbf(h0, h1);
                smu[U_H1L + r0 * 72 + cp] = packbf(v0 - h0, v1 - h1);
                smu[U_H1H + r1 * 72 + cp] = packbf(h2, h3);
                smu[U_H1L + r1 * 72 + cp] = packbf(v2 - h2, v3 - h3);
            }
        }
        __syncthreads();

        // ============ GEMM2: D2 = h1 @ W2 + b2 (8 k16-steps) ============
        #pragma unroll
        for (int f = 0; f < 4; f++) {
            const float2 bv = *reinterpret_cast<const float2*>(
                sm + F_B2 + jw + f * 8 + tg * 2);
            #pragma unroll
            for (int mi = 0; mi < 2; mi++) {
                d[f][mi][0] = bv.x; d[f][mi][1] = bv.y;
                d[f][mi][2] = bv.x; d[f][mi][3] = bv.y;
            }
        }
        #pragma unroll 1
        for (int s = 0; s < 8; s++) {
            const int ab = s * 8 + 2 * tg;
            uint32_t ah[2][4], al[2][4];
            #pragma unroll
            for (int mi = 0; mi < 2; mi++) {
                const int r0 = (arow + 16 * mi) * 72 + ab;
                const int r1 = r0 + 8 * 72;
                uint2 v0 = *reinterpret_cast<const uint2*>(smu + U_H1H + r0);
                uint2 v1 = *reinterpret_cast<const uint2*>(smu + U_H1H + r1);
                uint2 u0 = *reinterpret_cast<const uint2*>(smu + U_H1L + r0);
                uint2 u1 = *reinterpret_cast<const uint2*>(smu + U_H1L + r1);
                ah[mi][0] = v0.x; ah[mi][1] = v1.x; ah[mi][2] = v0.y; ah[mi][3] = v1.y;
                al[mi][0] = u0.x; al[mi][1] = u1.x; al[mi][2] = u0.y; al[mi][3] = u1.y;
            }
            const int fb = U_W2F / 4 + (s * 16 + ch * 4) * 32 + lane;
            #pragma unroll
            for (int f = 0; f < 4; f++) {
                const uint4 w = sm4[fb + f * 32];
                #pragma unroll
                for (int mi = 0; mi < 2; mi++) {
                    mmab(d[f][mi], ah[mi], w.x, w.y);
                    mmab(d[f][mi], al[mi], w.x, w.y);
                    mmab(d[f][mi], ah[mi], w.z, w.w);
                }
            }
        }

        // ============ epilogue: relu + W3 dot + reduce ============
        {
            float s0[2] = {0.0f, 0.0f}, s1[2] = {0.0f, 0.0f};
            #pragma unroll
            for (int f = 0; f < 4; f++) {
                const int jc = jw + f * 8 + tg * 2;
                const float w3a = sm[F_W3 + jc];
                const float w3b = sm[F_W3 + jc + 1];
                #pragma unroll
                for (int mi = 0; mi < 2; mi++) {
                    s0[mi] = fmaf(fmaxf(d[f][mi][0], 0.0f), w3a, s0[mi]);
                    s0[mi] = fmaf(fmaxf(d[f][mi][1], 0.0f), w3b, s0[mi]);
                    s1[mi] = fmaf(fmaxf(d[f][mi][2], 0.0f), w3a, s1[mi]);
                    s1[mi] = fmaf(fmaxf(d[f][mi][3], 0.0f), w3b, s1[mi]);
                }
            }
            #pragma unroll
            for (int mi = 0; mi < 2; mi++) {
                s0[mi] += __shfl_xor_sync(0xFFFFFFFF, s0[mi], 1);
                s0[mi] += __shfl_xor_sync(0xFFFFFFFF, s0[mi], 2);
                s1[mi] += __shfl_xor_sync(0xFFFFFFFF, s1[mi], 1);
                s1[mi] += __shfl_xor_sync(0xFFFFFFFF, s1[mi], 2);
            }
            if (tg == 0) {
                #pragma unroll
                for (int mi = 0; mi < 2; mi++) {
                    sm[F_PART + (arow + 16 * mi) * 5 + ch]     = s0[mi];
                    sm[F_PART + (arow + 16 * mi + 8) * 5 + ch] = s1[mi];
                }
            }
        }
        __syncthreads();

        if (tid < 128) {
            const float* pr = sm + F_PART + tid * 5;
            out[t * 128 + tid] = pr[0] + pr[1] + pr[2] + pr[3] + sm[F_B3];
        }
        // next-iter feat writes are fenced by the gather-phase __syncthreads
    }
}

extern "C" void kernel_launch(void* const* d_in, const int* in_sizes, int n_in,
                              void* d_out, int out_size)
{
    const float* x     = (const float*)d_in[0];
    const float* grids = (const float*)d_in[1];
    const float* W1    = (const float*)d_in[2];
    const float* b1    = (const float*)d_in[3];
    const float* W2    = (const float*)d_in[4];
    const float* b2    = (const float*)d_in[5];
    const float* W3    = (const float*)d_in[6];
    const float* b3    = (const float*)d_in[7];
    float* out = (float*)d_out;
    (void)in_sizes; (void)n_in; (void)out_size;

    cudaFuncSetAttribute(Model_61065845014888_kernel,
                         cudaFuncAttributeMaxDynamicSharedMemorySize, SMEM_BYTES);

    repack_kernel<<<(16 * GC + 255) / 256, 256>>>(grids);
    Model_61065845014888_kernel<<<NCTA, TPB, SMEM_BYTES>>>(
        x, W1, b1, W2, b2, W3, b3, out);
}

// round 12
// speedup vs baseline: 1.0252x; 1.0252x over previous
#include <cuda_runtime.h>
#include <cuda_bf16.h>
#include <cstdint>

// ---------------------------------------------------------------------------
// Instant-NGP MLP via mma.sync m16n8k16 BF16, split-bf16 (3-term).
// Round 12: round-10 structure + LDS instruction diet:
//   - weight hi/lo fragments fused in one uint4 (LDS.128)
//   - activation hi/lo interleaved (LDS.64 / STS.64)
// Grid y-pair repack retained. 16x64 warp tile, static schedule.
// ---------------------------------------------------------------------------

#define NPTS    2097152
#define NTILES  (NPTS / 128)     // 16384
#define TPB     512
#define NCTA    148
#define GS      513
#define GC      (GS * GS)

// SMEM map in u32 units
#define U_W1F   0                 // uint4[1024]  = 4096 u32
#define U_W2F   4096              // uint4[4096]  = 16384 u32
#define U_FEAT  20480             // 128*40 = 5120 (hi/lo interleaved)
#define U_H1    25600             // 128*136 = 17408 (hi/lo interleaved)
#define F_B1    43008
#define F_B2    43136
#define F_W3    43264
#define F_B3    43392             // 4
#define F_PART  43396             // 256
#define SM_U32  43652
#define SMEM_BYTES (SM_U32 * 4)   // 174608 B

// y-pair packed grid: P[l][i][j] = (g[i][j].xy, g[i][j+1].xy)
__device__ float4 g_pack[16 * GC];

__device__ constexpr int kResTab[16] = {16, 20, 25, 32, 40, 50, 64, 80,
                                        101, 128, 161, 203, 256, 322, 406, 512};

__device__ __forceinline__ float bf16f(float v) {
    return __bfloat162float(__float2bfloat16_rn(v));
}
__device__ __forceinline__ uint32_t packbf(float e0, float e1) {
    __nv_bfloat162 t = __halves2bfloat162(__float2bfloat16_rn(e0),
                                          __float2bfloat16_rn(e1));
    return *reinterpret_cast<uint32_t*>(&t);
}

__device__ __forceinline__ void mmab(float* d, const uint32_t* a,
                                     uint32_t b0, uint32_t b1) {
    asm volatile(
        "mma.sync.aligned.m16n8k16.row.col.f32.bf16.bf16.f32 "
        "{%0,%1,%2,%3}, {%4,%5,%6,%7}, {%8,%9}, {%0,%1,%2,%3};"
        : "+f"(d[0]), "+f"(d[1]), "+f"(d[2]), "+f"(d[3])
        : "r"(a[0]), "r"(a[1]), "r"(a[2]), "r"(a[3]), "r"(b0), "r"(b1));
}

// grid repack: 2 float2 reads -> 1 aligned float4 (y-pair)
__global__ __launch_bounds__(256)
void repack_kernel(const float* __restrict__ grids) {
    int idx = blockIdx.x * 256 + threadIdx.x;
    if (idx >= 16 * GC) return;
    int j = idx % GS;
    int i = (idx / GS) % GS;
    int l = idx / GC;
    const float2* g = reinterpret_cast<const float2*>(grids) + (size_t)l * GC;
    float2 a = __ldg(g + i * GS + j);
    float2 b = __ldg(g + i * GS + min(j + 1, GS - 1));
    g_pack[idx] = make_float4(a.x, a.y, b.x, b.y);
}

// 4-level gather via packed grid: 2 LDG.128 per level
template <int L0>
__device__ __forceinline__ void gather4(float2 xy, float* f) {
    #pragma unroll
    for (int i = 0; i < 4; i++) {
        const int   ri = kResTab[L0 + i];
        const float rf = (float)ri;
        const float fx = xy.x * rf, fy = xy.y * rf;
        const float fxf = floorf(fx), fyf = floorf(fy);
        const float wx = fx - fxf, wy = fy - fyf;
        int ix0 = min(max((int)fxf, 0), ri);
        int iy0 = min(max((int)fyf, 0), ri);
        int ix1 = min(ix0 + 1, ri);
        const float4* P = g_pack + (size_t)(L0 + i) * GC;
        const float4 a = __ldg(P + ix0 * GS + iy0);
        const float4 b = __ldg(P + ix1 * GS + iy0);
        const float owx = 1.0f - wx, owy = 1.0f - wy;
        const float t00 = a.x * owx + b.x * wx;
        const float t01 = a.y * owx + b.y * wx;
        const float t10 = a.z * owx + b.z * wx;
        const float t11 = a.w * owx + b.w * wx;
        f[2 * i + 0] = t00 * owy + t10 * wy;
        f[2 * i + 1] = t01 * owy + t11 * wy;
    }
}

__global__ __launch_bounds__(TPB, 1)
void Model_61065845014888_kernel(
    const float* __restrict__ x,
    const float* __restrict__ W1, const float* __restrict__ b1,
    const float* __restrict__ W2, const float* __restrict__ b2,
    const float* __restrict__ W3, const float* __restrict__ b3,
    float* __restrict__ out)
{
    extern __shared__ float sm[];
    uint32_t* smu = reinterpret_cast<uint32_t*>(sm);
    uint4*    sm4 = reinterpret_cast<uint4*>(sm);
    const int tid = threadIdx.x;

    // ---- stage weights: fused hi/lo uint4 fragments, once ----
    // uint4 q: ln = q&31, g = (q>>5)&15, s = q>>9
    //   k0 = s*16 + 2*(ln&3), k1 = k0+8, j = g*8 + (ln>>2)
    //   components: (hi_r0, hi_r1, lo_r0, lo_r1)
    for (int q = tid; q < 1024; q += TPB) {
        int ln = q & 31, g = (q >> 5) & 15, s = q >> 9;
        int k0 = s * 16 + 2 * (ln & 3), k1 = k0 + 8;
        int j = g * 8 + (ln >> 2);
        float w00 = W1[k0 * 128 + j], w01 = W1[(k0 + 1) * 128 + j];
        float w10 = W1[k1 * 128 + j], w11 = W1[(k1 + 1) * 128 + j];
        float h00 = bf16f(w00), h01 = bf16f(w01);
        float h10 = bf16f(w10), h11 = bf16f(w11);
        sm4[U_W1F / 4 + q] = make_uint4(
            packbf(h00, h01), packbf(h10, h11),
            packbf(w00 - h00, w01 - h01), packbf(w10 - h10, w11 - h11));
    }
    for (int q = tid; q < 4096; q += TPB) {
        int ln = q & 31, g = (q >> 5) & 15, s = q >> 9;
        int k0 = s * 16 + 2 * (ln & 3), k1 = k0 + 8;
        int j = g * 8 + (ln >> 2);
        float w00 = W2[k0 * 128 + j], w01 = W2[(k0 + 1) * 128 + j];
        float w10 = W2[k1 * 128 + j], w11 = W2[(k1 + 1) * 128 + j];
        float h00 = bf16f(w00), h01 = bf16f(w01);
        float h10 = bf16f(w10), h11 = bf16f(w11);
        sm4[U_W2F / 4 + q] = make_uint4(
            packbf(h00, h01), packbf(h10, h11),
            packbf(w00 - h00, w01 - h01), packbf(w10 - h10, w11 - h11));
    }
    if (tid < 128) {
        sm[F_B1 + tid] = b1[tid];
        sm[F_B2 + tid] = b2[tid];
        sm[F_W3 + tid] = W3[tid];
    }
    if (tid == 0) sm[F_B3] = b3[0];

    const int wid  = tid >> 5;
    const int lane = tid & 31;
    const int rg   = wid & 7;          // 16-row group
    const int ch   = wid >> 3;         // 64-col half
    const int tg   = lane & 3;
    const int gid  = lane >> 2;
    const int arow = rg * 16 + gid;
    const int jw   = ch * 64;

    const int gpt = tid >> 2;
    const int gq  = tid & 3;

    __syncthreads();

    for (int t = blockIdx.x; t < NTILES; t += NCTA) {
        // ==== gather -> interleaved split-bf16 feat (stride 40 u32) ====
        {
            const int p = t * 128 + gpt;
            const float2 xy = __ldg(reinterpret_cast<const float2*>(x) + p);
            float f[8];
            switch (gq) {
                case 0: gather4<0>(xy, f);  break;
                case 1: gather4<4>(xy, f);  break;
                case 2: gather4<8>(xy, f);  break;
                default: gather4<12>(xy, f); break;
            }
            uint32_t hi[4], lo[4];
            #pragma unroll
            for (int c = 0; c < 4; c++) {
                float h0 = bf16f(f[2*c]), h1 = bf16f(f[2*c+1]);
                hi[c] = packbf(h0, h1);
                lo[c] = packbf(f[2*c] - h0, f[2*c+1] - h1);
            }
            const int cb = U_FEAT + gpt * 40 + gq * 8;
            *reinterpret_cast<uint4*>(smu + cb) =
                make_uint4(hi[0], lo[0], hi[1], lo[1]);
            *reinterpret_cast<uint4*>(smu + cb + 4) =
                make_uint4(hi[2], lo[2], hi[3], lo[3]);
        }
        __syncthreads();

        float d[8][4];

        // ==== GEMM1: D1 = feat @ W1 + b1 (2 k16-steps) ====
        #pragma unroll
        for (int f = 0; f < 8; f++) {
            const float2 bv = *reinterpret_cast<const float2*>(
                sm + F_B1 + jw + f * 8 + tg * 2);
            d[f][0] = bv.x; d[f][1] = bv.y;
            d[f][2] = bv.x; d[f][3] = bv.y;
        }
        #pragma unroll
        for (int s = 0; s < 2; s++) {
            const int acol = s * 8 + tg;
            uint32_t ah[4], al[4];
            {
                uint2 v0 = *reinterpret_cast<const uint2*>(
                    smu + U_FEAT + arow * 40 + 2 * acol);
                uint2 v1 = *reinterpret_cast<const uint2*>(
                    smu + U_FEAT + (arow + 8) * 40 + 2 * acol);
                uint2 v2 = *reinterpret_cast<const uint2*>(
                    smu + U_FEAT + arow * 40 + 2 * (acol + 4));
                uint2 v3 = *reinterpret_cast<const uint2*>(
                    smu + U_FEAT + (arow + 8) * 40 + 2 * (acol + 4));
                ah[0] = v0.x; al[0] = v0.y;
                ah[1] = v1.x; al[1] = v1.y;
                ah[2] = v2.x; al[2] = v2.y;
                ah[3] = v3.x; al[3] = v3.y;
            }
            const int qb = U_W1F / 4 + (s * 16 + ch * 8) * 32 + lane;
            #pragma unroll
            for (int f = 0; f < 8; f++) {
                const uint4 w = sm4[qb + f * 32];
                mmab(d[f], ah, w.x, w.y);
                mmab(d[f], al, w.x, w.y);
                mmab(d[f], ah, w.z, w.w);
            }
        }

        // relu + interleaved split-store h1 (stride 136 u32)
        #pragma unroll
        for (int f = 0; f < 8; f++) {
            const int jc = jw / 2 + f * 4 + tg;      // logical u32 col
            float v0 = fmaxf(d[f][0], 0.0f), v1 = fmaxf(d[f][1], 0.0f);
            float v2 = fmaxf(d[f][2], 0.0f), v3 = fmaxf(d[f][3], 0.0f);
            float h0 = bf16f(v0), h1 = bf16f(v1), h2 = bf16f(v2), h3 = bf16f(v3);
            *reinterpret_cast<uint2*>(smu + U_H1 + arow * 136 + 2 * jc) =
                make_uint2(packbf(h0, h1), packbf(v0 - h0, v1 - h1));
            *reinterpret_cast<uint2*>(smu + U_H1 + (arow + 8) * 136 + 2 * jc) =
                make_uint2(packbf(h2, h3), packbf(v2 - h2, v3 - h3));
        }
        __syncthreads();

        // ==== GEMM2: D2 = h1 @ W2 + b2 (8 k16-steps) ====
        #pragma unroll
        for (int f = 0; f < 8; f++) {
            const float2 bv = *reinterpret_cast<const float2*>(
                sm + F_B2 + jw + f * 8 + tg * 2);
            d[f][0] = bv.x; d[f][1] = bv.y;
            d[f][2] = bv.x; d[f][3] = bv.y;
        }
        #pragma unroll 2
        for (int s = 0; s < 8; s++) {
            const int acol = s * 8 + tg;
            uint32_t ah[4], al[4];
            {
                uint2 v0 = *reinterpret_cast<const uint2*>(
                    smu + U_H1 + arow * 136 + 2 * acol);
                uint2 v1 = *reinterpret_cast<const uint2*>(
                    smu + U_H1 + (arow + 8) * 136 + 2 * acol);
                uint2 v2 = *reinterpret_cast<const uint2*>(
                    smu + U_H1 + arow * 136 + 2 * (acol + 4));
                uint2 v3 = *reinterpret_cast<const uint2*>(
                    smu + U_H1 + (arow + 8) * 136 + 2 * (acol + 4));
                ah[0] = v0.x; al[0] = v0.y;
                ah[1] = v1.x; al[1] = v1.y;
                ah[2] = v2.x; al[2] = v2.y;
                ah[3] = v3.x; al[3] = v3.y;
            }
            const int qb = U_W2F / 4 + (s * 16 + ch * 8) * 32 + lane;
            #pragma unroll
            for (int f = 0; f < 8; f++) {
                const uint4 w = sm4[qb + f * 32];
                mmab(d[f], ah, w.x, w.y);
                mmab(d[f], al, w.x, w.y);
                mmab(d[f], ah, w.z, w.w);
            }
        }

        // ==== epilogue: relu + W3 dot + reduce ====
        {
            float slo = 0.0f, shi = 0.0f;
            #pragma unroll
            for (int f = 0; f < 8; f++) {
                const int jc = jw + f * 8 + tg * 2;
                const float w3a = sm[F_W3 + jc];
                const float w3b = sm[F_W3 + jc + 1];
                slo = fmaf(fmaxf(d[f][0], 0.0f), w3a, slo);
                slo = fmaf(fmaxf(d[f][1], 0.0f), w3b, slo);
                shi = fmaf(fmaxf(d[f][2], 0.0f), w3a, shi);
                shi = fmaf(fmaxf(d[f][3], 0.0f), w3b, shi);
            }
            slo += __shfl_xor_sync(0xFFFFFFFF, slo, 1);
            slo += __shfl_xor_sync(0xFFFFFFFF, slo, 2);
            shi += __shfl_xor_sync(0xFFFFFFFF, shi, 1);
            shi += __shfl_xor_sync(0xFFFFFFFF, shi, 2);
            if (tg == 0) {
                sm[F_PART + arow * 2 + ch]       = slo;
                sm[F_PART + (arow + 8) * 2 + ch] = shi;
            }
        }
        __syncthreads();

        if (tid < 128)
            out[t * 128 + tid] = sm[F_PART + tid * 2]
                               + sm[F_PART + tid * 2 + 1]
                               + sm[F_B3];
        // next-iter feat writes fenced by the gather-phase __syncthreads
    }
}

extern "C" void kernel_launch(void* const* d_in, const int* in_sizes, int n_in,
                              void* d_out, int out_size)
{
    const float* x     = (const float*)d_in[0];
    const float* grids = (const float*)d_in[1];
    const float* W1    = (const float*)d_in[2];
    const float* b1    = (const float*)d_in[3];
    const float* W2    = (const float*)d_in[4];
    const float* b2    = (const float*)d_in[5];
    const float* W3    = (const float*)d_in[6];
    const float* b3    = (const float*)d_in[7];
    float* out = (float*)d_out;
    (void)in_sizes; (void)n_in; (void)out_size;

    cudaFuncSetAttribute(Model_61065845014888_kernel,
                         cudaFuncAttributeMaxDynamicSharedMemorySize, SMEM_BYTES);

    repack_kernel<<<(16 * GC + 255) / 256, 256>>>(grids);
    Model_61065845014888_kernel<<<NCTA, TPB, SMEM_BYTES>>>(
        x, W1, b1, W2, b2, W3, b3, out);
}

// round 13
// speedup vs baseline: 1.1505x; 1.1222x over previous
#include <cuda_runtime.h>
#include <cuda_bf16.h>
#include <cstdint>

// ---------------------------------------------------------------------------
// Instant-NGP MLP via mma.sync m16n8k16 BF16, split-bf16 (3-term).
// Round 13: round-10 structure verbatim, gather de-diverged:
// level-group is warp-uniform (gq = wid&3), all 32 lanes active on one path.
// Grid y-pair repack retained. 16x64 warp tile, static schedule.
// ---------------------------------------------------------------------------

#define NPTS    2097152
#define NTILES  (NPTS / 128)     // 16384
#define TPB     512
#define NCTA    148
#define GS      513
#define GC      (GS * GS)

// SMEM map in u32 units
#define U_W1FH  0                 // 2048
#define U_W1FL  2048
#define U_W2FH  4096              // 8192
#define U_W2FL  12288
#define U_FEATH 20480             // 128*20 = 2560
#define U_FEATL 23040
#define U_H1H   25600             // 128*68 = 8704
#define U_H1L   34304
#define F_B1    43008
#define F_B2    43136
#define F_W3    43264
#define F_B3    43392             // 4
#define F_PART  43396             // 256
#define SM_U32  43652
#define SMEM_BYTES (SM_U32 * 4)   // 174608 B

// y-pair packed grid: P[l][i][j] = (g[i][j].xy, g[i][j+1].xy)
__device__ float4 g_pack[16 * GC];

__device__ constexpr int kResTab[16] = {16, 20, 25, 32, 40, 50, 64, 80,
                                        101, 128, 161, 203, 256, 322, 406, 512};

__device__ __forceinline__ float bf16f(float v) {
    return __bfloat162float(__float2bfloat16_rn(v));
}
__device__ __forceinline__ uint32_t packbf(float e0, float e1) {
    __nv_bfloat162 t = __halves2bfloat162(__float2bfloat16_rn(e0),
                                          __float2bfloat16_rn(e1));
    return *reinterpret_cast<uint32_t*>(&t);
}

__device__ __forceinline__ void mmab(float* d, const uint32_t* a,
                                     uint32_t b0, uint32_t b1) {
    asm volatile(
        "mma.sync.aligned.m16n8k16.row.col.f32.bf16.bf16.f32 "
        "{%0,%1,%2,%3}, {%4,%5,%6,%7}, {%8,%9}, {%0,%1,%2,%3};"
        : "+f"(d[0]), "+f"(d[1]), "+f"(d[2]), "+f"(d[3])
        : "r"(a[0]), "r"(a[1]), "r"(a[2]), "r"(a[3]), "r"(b0), "r"(b1));
}

// grid repack: 2 float2 reads -> 1 aligned float4 (y-pair)
__global__ __launch_bounds__(256)
void repack_kernel(const float* __restrict__ grids) {
    int idx = blockIdx.x * 256 + threadIdx.x;
    if (idx >= 16 * GC) return;
    int j = idx % GS;
    int i = (idx / GS) % GS;
    int l = idx / GC;
    const float2* g = reinterpret_cast<const float2*>(grids) + (size_t)l * GC;
    float2 a = __ldg(g + i * GS + j);
    float2 b = __ldg(g + i * GS + min(j + 1, GS - 1));
    g_pack[idx] = make_float4(a.x, a.y, b.x, b.y);
}

// 4-level gather via packed grid: 2 LDG.128 per level
template <int L0>
__device__ __forceinline__ void gather4(float2 xy, float* f) {
    #pragma unroll
    for (int i = 0; i < 4; i++) {
        const int   ri = kResTab[L0 + i];
        const float rf = (float)ri;
        const float fx = xy.x * rf, fy = xy.y * rf;
        const float fxf = floorf(fx), fyf = floorf(fy);
        const float wx = fx - fxf, wy = fy - fyf;
        int ix0 = min(max((int)fxf, 0), ri);
        int iy0 = min(max((int)fyf, 0), ri);
        int ix1 = min(ix0 + 1, ri);
        const float4* P = g_pack + (size_t)(L0 + i) * GC;
        const float4 a = __ldg(P + ix0 * GS + iy0);
        const float4 b = __ldg(P + ix1 * GS + iy0);
        const float owx = 1.0f - wx, owy = 1.0f - wy;
        const float t00 = a.x * owx + b.x * wx;
        const float t01 = a.y * owx + b.y * wx;
        const float t10 = a.z * owx + b.z * wx;
        const float t11 = a.w * owx + b.w * wx;
        f[2 * i + 0] = t00 * owy + t10 * wy;
        f[2 * i + 1] = t01 * owy + t11 * wy;
    }
}

__global__ __launch_bounds__(TPB, 1)
void Model_61065845014888_kernel(
    const float* __restrict__ x,
    const float* __restrict__ W1, const float* __restrict__ b1,
    const float* __restrict__ W2, const float* __restrict__ b2,
    const float* __restrict__ W3, const float* __restrict__ b3,
    float* __restrict__ out)
{
    extern __shared__ float sm[];
    uint32_t* smu = reinterpret_cast<uint32_t*>(sm);
    const int tid = threadIdx.x;

    // ---- stage split-bf16 weight fragments, once ----
    for (int i = tid; i < 2048; i += TPB) {
        int r = i & 1, ln = (i >> 1) & 31, g = (i >> 6) & 15, s = i >> 10;
        int k = s * 16 + 2 * (ln & 3) + 8 * r;
        int j = g * 8 + (ln >> 2);
        float w0 = W1[k * 128 + j], w1 = W1[(k + 1) * 128 + j];
        float h0 = bf16f(w0), h1 = bf16f(w1);
        smu[U_W1FH + i] = packbf(h0, h1);
        smu[U_W1FL + i] = packbf(w0 - h0, w1 - h1);
    }
    for (int i = tid; i < 8192; i += TPB) {
        int r = i & 1, ln = (i >> 1) & 31, g = (i >> 6) & 15, s = i >> 10;
        int k = s * 16 + 2 * (ln & 3) + 8 * r;
        int j = g * 8 + (ln >> 2);
        float w0 = W2[k * 128 + j], w1 = W2[(k + 1) * 128 + j];
        float h0 = bf16f(w0), h1 = bf16f(w1);
        smu[U_W2FH + i] = packbf(h0, h1);
        smu[U_W2FL + i] = packbf(w0 - h0, w1 - h1);
    }
    if (tid < 128) {
        sm[F_B1 + tid] = b1[tid];
        sm[F_B2 + tid] = b2[tid];
        sm[F_W3 + tid] = W3[tid];
    }
    if (tid == 0) sm[F_B3] = b3[0];

    const int wid  = tid >> 5;
    const int lane = tid & 31;
    const int rg   = wid & 7;
    const int ch   = wid >> 3;
    const int tg   = lane & 3;
    const int gid  = lane >> 2;
    const int arow = rg * 16 + gid;
    const int jw   = ch * 64;

    // warp-uniform gather mapping: warp handles 32 points x 4 levels
    const int gq  = wid & 3;                // level group (UNIFORM in warp)
    const int gpt = (wid >> 2) * 32 + lane; // point 0..127

    __syncthreads();

    for (int t = blockIdx.x; t < NTILES; t += NCTA) {
        // ============ gather -> split bf16 feat (stride 20 u32) ============
        {
            const int p = t * 128 + gpt;
            const float2 xy = __ldg(reinterpret_cast<const float2*>(x) + p);
            float f[8];
            switch (gq) {                    // warp-uniform: no divergence
                case 0: gather4<0>(xy, f);  break;
                case 1: gather4<4>(xy, f);  break;
                case 2: gather4<8>(xy, f);  break;
                default: gather4<12>(xy, f); break;
            }
            uint32_t hi[4], lo[4];
            #pragma unroll
            for (int c = 0; c < 4; c++) {
                float h0 = bf16f(f[2*c]), h1 = bf16f(f[2*c+1]);
                hi[c] = packbf(h0, h1);
                lo[c] = packbf(f[2*c] - h0, f[2*c+1] - h1);
            }
            *reinterpret_cast<uint4*>(smu + U_FEATH + gpt * 20 + gq * 4) =
                make_uint4(hi[0], hi[1], hi[2], hi[3]);
            *reinterpret_cast<uint4*>(smu + U_FEATL + gpt * 20 + gq * 4) =
                make_uint4(lo[0], lo[1], lo[2], lo[3]);
        }
        __syncthreads();

        float d[8][4];

        // ============ GEMM1: D1 = feat @ W1 + b1 (2 k16-steps) ============
        #pragma unroll
        for (int f = 0; f < 8; f++) {
            const float2 bv = *reinterpret_cast<const float2*>(
                sm + F_B1 + jw + f * 8 + tg * 2);
            d[f][0] = bv.x; d[f][1] = bv.y;
            d[f][2] = bv.x; d[f][3] = bv.y;
        }
        #pragma unroll
        for (int s = 0; s < 2; s++) {
            const int acol = s * 8 + tg;
            uint32_t ah[4], al[4];
            ah[0] = smu[U_FEATH + arow * 20 + acol];
            ah[1] = smu[U_FEATH + (arow + 8) * 20 + acol];
            ah[2] = smu[U_FEATH + arow * 20 + acol + 4];
            ah[3] = smu[U_FEATH + (arow + 8) * 20 + acol + 4];
            al[0] = smu[U_FEATL + arow * 20 + acol];
            al[1] = smu[U_FEATL + (arow + 8) * 20 + acol];
            al[2] = smu[U_FEATL + arow * 20 + acol + 4];
            al[3] = smu[U_FEATL + (arow + 8) * 20 + acol + 4];
            const int fb = ((s * 16 + ch * 8) * 32 + lane) * 2;
            #pragma unroll
            for (int f = 0; f < 8; f++) {
                const uint2 wh = *reinterpret_cast<const uint2*>(
                    smu + U_W1FH + fb + f * 64);
                const uint2 wl = *reinterpret_cast<const uint2*>(
                    smu + U_W1FL + fb + f * 64);
                mmab(d[f], ah, wh.x, wh.y);
                mmab(d[f], al, wh.x, wh.y);
                mmab(d[f], ah, wl.x, wl.y);
            }
        }

        // relu + split-store h1 (stride 68 u32)
        #pragma unroll
        for (int f = 0; f < 8; f++) {
            const int jc = jw / 2 + f * 4 + tg;
            float v0 = fmaxf(d[f][0], 0.0f), v1 = fmaxf(d[f][1], 0.0f);
            float v2 = fmaxf(d[f][2], 0.0f), v3 = fmaxf(d[f][3], 0.0f);
            float h0 = bf16f(v0), h1 = bf16f(v1), h2 = bf16f(v2), h3 = bf16f(v3);
            smu[U_H1H + arow * 68 + jc]       = packbf(h0, h1);
            smu[U_H1L + arow * 68 + jc]       = packbf(v0 - h0, v1 - h1);
            smu[U_H1H + (arow + 8) * 68 + jc] = packbf(h2, h3);
            smu[U_H1L + (arow + 8) * 68 + jc] = packbf(v2 - h2, v3 - h3);
        }
        __syncthreads();

        // ============ GEMM2: D2 = h1 @ W2 + b2 (8 k16-steps) ============
        #pragma unroll
        for (int f = 0; f < 8; f++) {
            const float2 bv = *reinterpret_cast<const float2*>(
                sm + F_B2 + jw + f * 8 + tg * 2);
            d[f][0] = bv.x; d[f][1] = bv.y;
            d[f][2] = bv.x; d[f][3] = bv.y;
        }
        #pragma unroll 1
        for (int s = 0; s < 8; s++) {
            const int acol = s * 8 + tg;
            uint32_t ah[4], al[4];
            ah[0] = smu[U_H1H + arow * 68 + acol];
            ah[1] = smu[U_H1H + (arow + 8) * 68 + acol];
            ah[2] = smu[U_H1H + arow * 68 + acol + 4];
            ah[3] = smu[U_H1H + (arow + 8) * 68 + acol + 4];
            al[0] = smu[U_H1L + arow * 68 + acol];
            al[1] = smu[U_H1L + (arow + 8) * 68 + acol];
            al[2] = smu[U_H1L + arow * 68 + acol + 4];
            al[3] = smu[U_H1L + (arow + 8) * 68 + acol + 4];
            const int fb = ((s * 16 + ch * 8) * 32 + lane) * 2;
            #pragma unroll
            for (int f = 0; f < 8; f++) {
                const uint2 wh = *reinterpret_cast<const uint2*>(
                    smu + U_W2FH + fb + f * 64);
                const uint2 wl = *reinterpret_cast<const uint2*>(
                    smu + U_W2FL + fb + f * 64);
                mmab(d[f], ah, wh.x, wh.y);
                mmab(d[f], al, wh.x, wh.y);
                mmab(d[f], ah, wl.x, wl.y);
            }
        }

        // ============ epilogue: relu + W3 dot + reduce ============
        {
            float slo = 0.0f, shi = 0.0f;
            #pragma unroll
            for (int f = 0; f < 8; f++) {
                const int jc = jw + f * 8 + tg * 2;
                const float w3a = sm[F_W3 + jc];
                const float w3b = sm[F_W3 + jc + 1];
                slo = fmaf(fmaxf(d[f][0], 0.0f), w3a, slo);
                slo = fmaf(fmaxf(d[f][1], 0.0f), w3b, slo);
                shi = fmaf(fmaxf(d[f][2], 0.0f), w3a, shi);
                shi = fmaf(fmaxf(d[f][3], 0.0f), w3b, shi);
            }
            slo += __shfl_xor_sync(0xFFFFFFFF, slo, 1);
            slo += __shfl_xor_sync(0xFFFFFFFF, slo, 2);
            shi += __shfl_xor_sync(0xFFFFFFFF, shi, 1);
            shi += __shfl_xor_sync(0xFFFFFFFF, shi, 2);
            if (tg == 0) {
                sm[F_PART + arow * 2 + ch]       = slo;
                sm[F_PART + (arow + 8) * 2 + ch] = shi;
            }
        }
        __syncthreads();

        if (tid < 128)
            out[t * 128 + tid] = sm[F_PART + tid * 2]
                               + sm[F_PART + tid * 2 + 1]
                               + sm[F_B3];
        // next-iter feat writes fenced by the gather-phase __syncthreads
    }
}

extern "C" void kernel_launch(void* const* d_in, const int* in_sizes, int n_in,
                              void* d_out, int out_size)
{
    const float* x     = (const float*)d_in[0];
    const float* grids = (const float*)d_in[1];
    const float* W1    = (const float*)d_in[2];
    const float* b1    = (const float*)d_in[3];
    const float* W2    = (const float*)d_in[4];
    const float* b2    = (const float*)d_in[5];
    const float* W3    = (const float*)d_in[6];
    const float* b3    = (const float*)d_in[7];
    float* out = (float*)d_out;
    (void)in_sizes; (void)n_in; (void)out_size;

    cudaFuncSetAttribute(Model_61065845014888_kernel,
                         cudaFuncAttributeMaxDynamicSharedMemorySize, SMEM_BYTES);

    repack_kernel<<<(16 * GC + 255) / 256, 256>>>(grids);
    Model_61065845014888_kernel<<<NCTA, TPB, SMEM_BYTES>>>(
        x, W1, b1, W2, b2, W3, b3, out);
}

// round 14
// speedup vs baseline: 1.4679x; 1.2759x over previous
#include <cuda_runtime.h>
#include <cuda_fp16.h>
#include <cstdint>

// ---------------------------------------------------------------------------
// Instant-NGP MLP via mma.sync m16n8k16 FP16 (f32 accum), 2-term split:
// A = Ah + Al (fp16 pair), B single fp16 plane. Features scaled x1024
// (folded into b1,b2; 1/1024 folded into W3) to keep A-lo in fp16 range.
// Round-13 mapping: warp-uniform gather, y-pair repacked grid, static sched.
// ---------------------------------------------------------------------------

#define NPTS    2097152
#define NTILES  (NPTS / 128)     // 16384
#define TPB     512
#define NCTA    148
#define GS      513
#define GC      (GS * GS)
#define SCALE   1024.0f
#define INVSCALE (1.0f / 1024.0f)

// SMEM map in u32 units
#define U_W1F   0                 // 2048 (single fp16 plane, frag-major)
#define U_W2F   2048              // 8192
#define U_FEATH 10240             // 128*20 = 2560
#define U_FEATL 12800             // 2560
#define U_H1H   15360             // 128*68 = 8704
#define U_H1L   24064             // 8704
#define F_B1    32768             // 128 (pre-scaled)
#define F_B2    32896             // 128 (pre-scaled)
#define F_W3    33024             // 128 (pre-divided by SCALE)
#define F_B3    33152             // 4
#define F_PART  33156             // 256
#define SM_U32  33412
#define SMEM_BYTES (SM_U32 * 4)   // 133648 B

// y-pair packed grid: P[l][i][j] = (g[i][j].xy, g[i][j+1].xy)
__device__ float4 g_pack[16 * GC];

__device__ constexpr int kResTab[16] = {16, 20, 25, 32, 40, 50, 64, 80,
                                        101, 128, 161, 203, 256, 322, 406, 512};

__device__ __forceinline__ uint32_t packh(float e0, float e1) {
    __half2 t = __floats2half2_rn(e0, e1);
    return *reinterpret_cast<uint32_t*>(&t);
}
// split v into fp16 hi + float residual
__device__ __forceinline__ void splith(float v, __half& hi, float& lo) {
    hi = __float2half_rn(v);
    lo = v - __half2float(hi);
}

__device__ __forceinline__ void mmah(float* d, const uint32_t* a,
                                     uint32_t b0, uint32_t b1) {
    asm volatile(
        "mma.sync.aligned.m16n8k16.row.col.f32.f16.f16.f32 "
        "{%0,%1,%2,%3}, {%4,%5,%6,%7}, {%8,%9}, {%0,%1,%2,%3};"
        : "+f"(d[0]), "+f"(d[1]), "+f"(d[2]), "+f"(d[3])
        : "r"(a[0]), "r"(a[1]), "r"(a[2]), "r"(a[3]), "r"(b0), "r"(b1));
}

// grid repack: 2 float2 reads -> 1 aligned float4 (y-pair)
__global__ __launch_bounds__(256)
void repack_kernel(const float* __restrict__ grids) {
    int idx = blockIdx.x * 256 + threadIdx.x;
    if (idx >= 16 * GC) return;
    int j = idx % GS;
    int i = (idx / GS) % GS;
    int l = idx / GC;
    const float2* g = reinterpret_cast<const float2*>(grids) + (size_t)l * GC;
    float2 a = __ldg(g + i * GS + j);
    float2 b = __ldg(g + i * GS + min(j + 1, GS - 1));
    g_pack[idx] = make_float4(a.x, a.y, b.x, b.y);
}

// 4-level gather via packed grid: 2 LDG.128 per level
template <int L0>
__device__ __forceinline__ void gather4(float2 xy, float* f) {
    #pragma unroll
    for (int i = 0; i < 4; i++) {
        const int   ri = kResTab[L0 + i];
        const float rf = (float)ri;
        const float fx = xy.x * rf, fy = xy.y * rf;
        const float fxf = floorf(fx), fyf = floorf(fy);
        const float wx = fx - fxf, wy = fy - fyf;
        int ix0 = min(max((int)fxf, 0), ri);
        int iy0 = min(max((int)fyf, 0), ri);
        int ix1 = min(ix0 + 1, ri);
        const float4* P = g_pack + (size_t)(L0 + i) * GC;
        const float4 a = __ldg(P + ix0 * GS + iy0);
        const float4 b = __ldg(P + ix1 * GS + iy0);
        const float owx = 1.0f - wx, owy = 1.0f - wy;
        const float t00 = a.x * owx + b.x * wx;
        const float t01 = a.y * owx + b.y * wx;
        const float t10 = a.z * owx + b.z * wx;
        const float t11 = a.w * owx + b.w * wx;
        f[2 * i + 0] = t00 * owy + t10 * wy;
        f[2 * i + 1] = t01 * owy + t11 * wy;
    }
}

__global__ __launch_bounds__(TPB, 1)
void Model_61065845014888_kernel(
    const float* __restrict__ x,
    const float* __restrict__ W1, const float* __restrict__ b1,
    const float* __restrict__ W2, const float* __restrict__ b2,
    const float* __restrict__ W3, const float* __restrict__ b3,
    float* __restrict__ out)
{
    extern __shared__ float sm[];
    uint32_t* smu = reinterpret_cast<uint32_t*>(sm);
    const int tid = threadIdx.x;

    // ---- stage single-plane fp16 weight fragments, once ----
    for (int i = tid; i < 2048; i += TPB) {
        int r = i & 1, ln = (i >> 1) & 31, g = (i >> 6) & 15, s = i >> 10;
        int k = s * 16 + 2 * (ln & 3) + 8 * r;
        int j = g * 8 + (ln >> 2);
        smu[U_W1F + i] = packh(W1[k * 128 + j], W1[(k + 1) * 128 + j]);
    }
    for (int i = tid; i < 8192; i += TPB) {
        int r = i & 1, ln = (i >> 1) & 31, g = (i >> 6) & 15, s = i >> 10;
        int k = s * 16 + 2 * (ln & 3) + 8 * r;
        int j = g * 8 + (ln >> 2);
        smu[U_W2F + i] = packh(W2[k * 128 + j], W2[(k + 1) * 128 + j]);
    }
    if (tid < 128) {
        sm[F_B1 + tid] = b1[tid] * SCALE;
        sm[F_B2 + tid] = b2[tid] * SCALE;
        sm[F_W3 + tid] = W3[tid] * INVSCALE;
    }
    if (tid == 0) sm[F_B3] = b3[0];

    const int wid  = tid >> 5;
    const int lane = tid & 31;
    const int rg   = wid & 7;
    const int ch   = wid >> 3;
    const int tg   = lane & 3;
    const int gid  = lane >> 2;
    const int arow = rg * 16 + gid;
    const int jw   = ch * 64;

    // warp-uniform gather mapping: warp handles 32 points x 4 levels
    const int gq  = wid & 3;
    const int gpt = (wid >> 2) * 32 + lane;

    __syncthreads();

    for (int t = blockIdx.x; t < NTILES; t += NCTA) {
        // ============ gather -> scaled split-fp16 feat (stride 20) =========
        {
            const int p = t * 128 + gpt;
            const float2 xy = __ldg(reinterpret_cast<const float2*>(x) + p);
            float f[8];
            switch (gq) {
                case 0: gather4<0>(xy, f);  break;
                case 1: gather4<4>(xy, f);  break;
                case 2: gather4<8>(xy, f);  break;
                default: gather4<12>(xy, f); break;
            }
            uint32_t hi[4], lo[4];
            #pragma unroll
            for (int c = 0; c < 4; c++) {
                float v0 = f[2*c] * SCALE, v1 = f[2*c+1] * SCALE;
                __half h0, h1; float l0, l1;
                splith(v0, h0, l0);
                splith(v1, h1, l1);
                hi[c] = packh(__half2float(h0), __half2float(h1));
                lo[c] = packh(l0, l1);
            }
            *reinterpret_cast<uint4*>(smu + U_FEATH + gpt * 20 + gq * 4) =
                make_uint4(hi[0], hi[1], hi[2], hi[3]);
            *reinterpret_cast<uint4*>(smu + U_FEATL + gpt * 20 + gq * 4) =
                make_uint4(lo[0], lo[1], lo[2], lo[3]);
        }
        __syncthreads();

        float d[8][4];

        // ============ GEMM1: D1 = feat @ W1 + b1 (2 k16-steps) ============
        #pragma unroll
        for (int f = 0; f < 8; f++) {
            const float2 bv = *reinterpret_cast<const float2*>(
                sm + F_B1 + jw + f * 8 + tg * 2);
            d[f][0] = bv.x; d[f][1] = bv.y;
            d[f][2] = bv.x; d[f][3] = bv.y;
        }
        #pragma unroll
        for (int s = 0; s < 2; s++) {
            const int acol = s * 8 + tg;
            uint32_t ah[4], al[4];
            ah[0] = smu[U_FEATH + arow * 20 + acol];
            ah[1] = smu[U_FEATH + (arow + 8) * 20 + acol];
            ah[2] = smu[U_FEATH + arow * 20 + acol + 4];
            ah[3] = smu[U_FEATH + (arow + 8) * 20 + acol + 4];
            al[0] = smu[U_FEATL + arow * 20 + acol];
            al[1] = smu[U_FEATL + (arow + 8) * 20 + acol];
            al[2] = smu[U_FEATL + arow * 20 + acol + 4];
            al[3] = smu[U_FEATL + (arow + 8) * 20 + acol + 4];
            const int fb = ((s * 16 + ch * 8) * 32 + lane) * 2;
            #pragma unroll
            for (int f = 0; f < 8; f++) {
                const uint2 w = *reinterpret_cast<const uint2*>(
                    smu + U_W1F + fb + f * 64);
                mmah(d[f], ah, w.x, w.y);
                mmah(d[f], al, w.x, w.y);
            }
        }

        // relu + split-store h1 (stride 68 u32); values stay SCALE-scaled
        #pragma unroll
        for (int f = 0; f < 8; f++) {
            const int jc = jw / 2 + f * 4 + tg;
            float v0 = fmaxf(d[f][0], 0.0f), v1 = fmaxf(d[f][1], 0.0f);
            float v2 = fmaxf(d[f][2], 0.0f), v3 = fmaxf(d[f][3], 0.0f);
            __half h0, h1, h2, h3; float l0, l1, l2, l3;
            splith(v0, h0, l0); splith(v1, h1, l1);
            splith(v2, h2, l2); splith(v3, h3, l3);
            smu[U_H1H + arow * 68 + jc] =
                packh(__half2float(h0), __half2float(h1));
            smu[U_H1L + arow * 68 + jc] = packh(l0, l1);
            smu[U_H1H + (arow + 8) * 68 + jc] =
                packh(__half2float(h2), __half2float(h3));
            smu[U_H1L + (arow + 8) * 68 + jc] = packh(l2, l3);
        }
        __syncthreads();

        // ============ GEMM2: D2 = h1 @ W2 + b2 (8 k16-steps) ============
        #pragma unroll
        for (int f = 0; f < 8; f++) {
            const float2 bv = *reinterpret_cast<const float2*>(
                sm + F_B2 + jw + f * 8 + tg * 2);
            d[f][0] = bv.x; d[f][1] = bv.y;
            d[f][2] = bv.x; d[f][3] = bv.y;
        }
        #pragma unroll 1
        for (int s = 0; s < 8; s++) {
            const int acol = s * 8 + tg;
            uint32_t ah[4], al[4];
            ah[0] = smu[U_H1H + arow * 68 + acol];
            ah[1] = smu[U_H1H + (arow + 8) * 68 + acol];
            ah[2] = smu[U_H1H + arow * 68 + acol + 4];
            ah[3] = smu[U_H1H + (arow + 8) * 68 + acol + 4];
            al[0] = smu[U_H1L + arow * 68 + acol];
            al[1] = smu[U_H1L + (arow + 8) * 68 + acol];
            al[2] = smu[U_H1L + arow * 68 + acol + 4];
            al[3] = smu[U_H1L + (arow + 8) * 68 + acol + 4];
            const int fb = ((s * 16 + ch * 8) * 32 + lane) * 2;
            #pragma unroll
            for (int f = 0; f < 8; f++) {
                const uint2 w = *reinterpret_cast<const uint2*>(
                    smu + U_W2F + fb + f * 64);
                mmah(d[f], ah, w.x, w.y);
                mmah(d[f], al, w.x, w.y);
            }
        }

        // ============ epilogue: relu + (W3/SCALE) dot + reduce ============
        {
            float slo = 0.0f, shi = 0.0f;
            #pragma unroll
            for (int f = 0; f < 8; f++) {
                const int jc = jw + f * 8 + tg * 2;
                const float w3a = sm[F_W3 + jc];
                const float w3b = sm[F_W3 + jc + 1];
                slo = fmaf(fmaxf(d[f][0], 0.0f), w3a, slo);
                slo = fmaf(fmaxf(d[f][1], 0.0f), w3b, slo);
                shi = fmaf(fmaxf(d[f][2], 0.0f), w3a, shi);
                shi = fmaf(fmaxf(d[f][3], 0.0f), w3b, shi);
            }
            slo += __shfl_xor_sync(0xFFFFFFFF, slo, 1);
            slo += __shfl_xor_sync(0xFFFFFFFF, slo, 2);
            shi += __shfl_xor_sync(0xFFFFFFFF, shi, 1);
            shi += __shfl_xor_sync(0xFFFFFFFF, shi, 2);
            if (tg == 0) {
                sm[F_PART + arow * 2 + ch]       = slo;
                sm[F_PART + (arow + 8) * 2 + ch] = shi;
            }
        }
        __syncthreads();

        if (tid < 128)
            out[t * 128 + tid] = sm[F_PART + tid * 2]
                               + sm[F_PART + tid * 2 + 1]
                               + sm[F_B3];
        // next-iter feat writes fenced by the gather-phase __syncthreads
    }
}

extern "C" void kernel_launch(void* const* d_in, const int* in_sizes, int n_in,
                              void* d_out, int out_size)
{
    const float* x     = (const float*)d_in[0];
    const float* grids = (const float*)d_in[1];
    const float* W1    = (const float*)d_in[2];
    const float* b1    = (const float*)d_in[3];
    const float* W2    = (const float*)d_in[4];
    const float* b2    = (const float*)d_in[5];
    const float* W3    = (const float*)d_in[6];
    const float* b3    = (const float*)d_in[7];
    float* out = (float*)d_out;
    (void)in_sizes; (void)n_in; (void)out_size;

    cudaFuncSetAttribute(Model_61065845014888_kernel,
                         cudaFuncAttributeMaxDynamicSharedMemorySize, SMEM_BYTES);

    repack_kernel<<<(16 * GC + 255) / 256, 256>>>(grids);
    Model_61065845014888_kernel<<<NCTA, TPB, SMEM_BYTES>>>(
        x, W1, b1, W2, b2, W3, b3, out);
}

// round 15
// speedup vs baseline: 1.5037x; 1.0244x over previous
#include <cuda_runtime.h>
#include <cuda_fp16.h>
#include <cstdint>

// ---------------------------------------------------------------------------
// Instant-NGP MLP via mma.sync m16n8k16 FP16 (f32 accum), 2-term A-split,
// features scaled x1024. Round 15: software-pipelined gather —
// corner LDGs for tile t+NCTA issued after h1 store, consumed after the
// epilogue (feat double-buffered). Warp-uniform level groups, y-pair repack.
// ---------------------------------------------------------------------------

#define NPTS    2097152
#define NTILES  (NPTS / 128)     // 16384
#define TPB     512
#define NCTA    148
#define GS      513
#define GC      (GS * GS)
#define SCALE   1024.0f
#define INVSCALE (1.0f / 1024.0f)

// SMEM map in u32 units
#define U_W1F   0                 // 2048 (fp16 plane, frag-major)
#define U_W2F   2048              // 8192
#define U_FEAT  10240             // 2 bufs x (H 2560 + L 2560) = 10240
#define FEAT_PL 2560
#define U_H1H   20480             // 128*68 = 8704
#define U_H1L   29184             // 8704
#define F_B1    37888
#define F_B2    38016
#define F_W3    38144
#define F_B3    38272             // 4
#define F_PART  38276             // 256
#define SM_U32  38532
#define SMEM_BYTES (SM_U32 * 4)   // 154128 B

// y-pair packed grid: P[l][i][j] = (g[i][j].xy, g[i][j+1].xy)
__device__ float4 g_pack[16 * GC];

__device__ constexpr int kResTab[16] = {16, 20, 25, 32, 40, 50, 64, 80,
                                        101, 128, 161, 203, 256, 322, 406, 512};

__device__ __forceinline__ uint32_t packh(float e0, float e1) {
    __half2 t = __floats2half2_rn(e0, e1);
    return *reinterpret_cast<uint32_t*>(&t);
}
__device__ __forceinline__ void splith(float v, __half& hi, float& lo) {
    hi = __float2half_rn(v);
    lo = v - __half2float(hi);
}

__device__ __forceinline__ void mmah(float* d, const uint32_t* a,
                                     uint32_t b0, uint32_t b1) {
    asm volatile(
        "mma.sync.aligned.m16n8k16.row.col.f32.f16.f16.f32 "
        "{%0,%1,%2,%3}, {%4,%5,%6,%7}, {%8,%9}, {%0,%1,%2,%3};"
        : "+f"(d[0]), "+f"(d[1]), "+f"(d[2]), "+f"(d[3])
        : "r"(a[0]), "r"(a[1]), "r"(a[2]), "r"(a[3]), "r"(b0), "r"(b1));
}

// pinned-issue-point 128-bit global load
__device__ __forceinline__ float4 ldg4(const float4* p) {
    float4 v;
    asm volatile("ld.global.nc.v4.f32 {%0,%1,%2,%3}, [%4];"
                 : "=f"(v.x), "=f"(v.y), "=f"(v.z), "=f"(v.w) : "l"(p));
    return v;
}

// grid repack: 2 float2 reads -> 1 aligned float4 (y-pair)
__global__ __launch_bounds__(256)
void repack_kernel(const float* __restrict__ grids) {
    int idx = blockIdx.x * 256 + threadIdx.x;
    if (idx >= 16 * GC) return;
    int j = idx % GS;
    int i = (idx / GS) % GS;
    int l = idx / GC;
    const float2* g = reinterpret_cast<const float2*>(grids) + (size_t)l * GC;
    float2 a = __ldg(g + i * GS + j);
    float2 b = __ldg(g + i * GS + min(j + 1, GS - 1));
    g_pack[idx] = make_float4(a.x, a.y, b.x, b.y);
}

// ---- pipelined gather phases (4 levels, warp-uniform base) ----
template <int L0>
__device__ __forceinline__ void gissue(float2 xy, float4* c) {
    #pragma unroll
    for (int i = 0; i < 4; i++) {
        const int   ri = kResTab[L0 + i];
        const float rf = (float)ri;
        int ix0 = min(max((int)floorf(xy.x * rf), 0), ri);
        int iy0 = min(max((int)floorf(xy.y * rf), 0), ri);
        int ix1 = min(ix0 + 1, ri);
        const float4* P = g_pack + (size_t)(L0 + i) * GC;
        c[2*i]   = ldg4(P + ix0 * GS + iy0);
        c[2*i+1] = ldg4(P + ix1 * GS + iy0);
    }
}
template <int L0>
__device__ __forceinline__ void gfinish(float2 xy, const float4* c, float* f) {
    #pragma unroll
    for (int i = 0; i < 4; i++) {
        const float rf = (float)kResTab[L0 + i];
        const float fx = xy.x * rf, fy = xy.y * rf;
        const float wx = fx - floorf(fx), wy = fy - floorf(fy);
        const float owx = 1.0f - wx, owy = 1.0f - wy;
        const float4 a = c[2*i], b = c[2*i+1];
        const float t00 = a.x * owx + b.x * wx;
        const float t01 = a.y * owx + b.y * wx;
        const float t10 = a.z * owx + b.z * wx;
        const float t11 = a.w * owx + b.w * wx;
        f[2*i+0] = t00 * owy + t10 * wy;
        f[2*i+1] = t01 * owy + t11 * wy;
    }
}

// scale + split + store one point's 8 features into a feat buffer
__device__ __forceinline__ void feat_store(uint32_t* smu, int bufbase,
                                           int gpt, int gq, const float* f) {
    uint32_t hi[4], lo[4];
    #pragma unroll
    for (int c = 0; c < 4; c++) {
        float v0 = f[2*c] * SCALE, v1 = f[2*c+1] * SCALE;
        __half h0, h1; float l0, l1;
        splith(v0, h0, l0);
        splith(v1, h1, l1);
        hi[c] = packh(__half2float(h0), __half2float(h1));
        lo[c] = packh(l0, l1);
    }
    *reinterpret_cast<uint4*>(smu + bufbase + gpt * 20 + gq * 4) =
        make_uint4(hi[0], hi[1], hi[2], hi[3]);
    *reinterpret_cast<uint4*>(smu + bufbase + FEAT_PL + gpt * 20 + gq * 4) =
        make_uint4(lo[0], lo[1], lo[2], lo[3]);
}

__global__ __launch_bounds__(TPB, 1)
void Model_61065845014888_kernel(
    const float* __restrict__ x,
    const float* __restrict__ W1, const float* __restrict__ b1,
    const float* __restrict__ W2, const float* __restrict__ b2,
    const float* __restrict__ W3, const float* __restrict__ b3,
    float* __restrict__ out)
{
    extern __shared__ float sm[];
    uint32_t* smu = reinterpret_cast<uint32_t*>(sm);
    const int tid = threadIdx.x;

    // ---- stage fp16 weight fragments, once ----
    for (int i = tid; i < 2048; i += TPB) {
        int r = i & 1, ln = (i >> 1) & 31, g = (i >> 6) & 15, s = i >> 10;
        int k = s * 16 + 2 * (ln & 3) + 8 * r;
        int j = g * 8 + (ln >> 2);
        smu[U_W1F + i] = packh(W1[k * 128 + j], W1[(k + 1) * 128 + j]);
    }
    for (int i = tid; i < 8192; i += TPB) {
        int r = i & 1, ln = (i >> 1) & 31, g = (i >> 6) & 15, s = i >> 10;
        int k = s * 16 + 2 * (ln & 3) + 8 * r;
        int j = g * 8 + (ln >> 2);
        smu[U_W2F + i] = packh(W2[k * 128 + j], W2[(k + 1) * 128 + j]);
    }
    if (tid < 128) {
        sm[F_B1 + tid] = b1[tid] * SCALE;
        sm[F_B2 + tid] = b2[tid] * SCALE;
        sm[F_W3 + tid] = W3[tid] * INVSCALE;
    }
    if (tid == 0) sm[F_B3] = b3[0];

    const int wid  = tid >> 5;
    const int lane = tid & 31;
    const int rg   = wid & 7;
    const int ch   = wid >> 3;
    const int tg   = lane & 3;
    const int gid  = lane >> 2;
    const int arow = rg * 16 + gid;
    const int jw   = ch * 64;

    const int gq  = wid & 3;                // warp-uniform level group
    const int gpt = (wid >> 2) * 32 + lane; // point 0..127

    // ---- prologue: gather tile blockIdx.x into feat buf 0 ----
    {
        const float2 xy = __ldg(reinterpret_cast<const float2*>(x)
                                + blockIdx.x * 128 + gpt);
        float4 c[8]; float f[8];
        switch (gq) {
            case 0: gissue<0>(xy, c);  gfinish<0>(xy, c, f);  break;
            case 1: gissue<4>(xy, c);  gfinish<4>(xy, c, f);  break;
            case 2: gissue<8>(xy, c);  gfinish<8>(xy, c, f);  break;
            default: gissue<12>(xy, c); gfinish<12>(xy, c, f); break;
        }
        feat_store(smu, U_FEAT, gpt, gq, f);
    }

    int buf = 0;
    for (int t = blockIdx.x; t < NTILES; t += NCTA, buf ^= 1) {
        const int  tn      = t + NCTA;
        const bool hasnext = tn < NTILES;
        const float2 xyn = __ldg(reinterpret_cast<const float2*>(x)
                                 + (hasnext ? tn : t) * 128 + gpt);

        __syncthreads();   // feat[buf] visible; weights staged (first iter)

        const int fbH = U_FEAT + buf * (2 * FEAT_PL);
        const int fbL = fbH + FEAT_PL;

        float d[8][4];

        // ============ GEMM1: D1 = feat @ W1 + b1 (2 k16-steps) ============
        #pragma unroll
        for (int f = 0; f < 8; f++) {
            const float2 bv = *reinterpret_cast<const float2*>(
                sm + F_B1 + jw + f * 8 + tg * 2);
            d[f][0] = bv.x; d[f][1] = bv.y;
            d[f][2] = bv.x; d[f][3] = bv.y;
        }
        #pragma unroll
        for (int s = 0; s < 2; s++) {
            const int acol = s * 8 + tg;
            uint32_t ah[4], al[4];
            ah[0] = smu[fbH + arow * 20 + acol];
            ah[1] = smu[fbH + (arow + 8) * 20 + acol];
            ah[2] = smu[fbH + arow * 20 + acol + 4];
            ah[3] = smu[fbH + (arow + 8) * 20 + acol + 4];
            al[0] = smu[fbL + arow * 20 + acol];
            al[1] = smu[fbL + (arow + 8) * 20 + acol];
            al[2] = smu[fbL + arow * 20 + acol + 4];
            al[3] = smu[fbL + (arow + 8) * 20 + acol + 4];
            const int fb = ((s * 16 + ch * 8) * 32 + lane) * 2;
            #pragma unroll
            for (int f = 0; f < 8; f++) {
                const uint2 w = *reinterpret_cast<const uint2*>(
                    smu + U_W1F + fb + f * 64);
                mmah(d[f], ah, w.x, w.y);
                mmah(d[f], al, w.x, w.y);
            }
        }

        // relu + split-store h1 (stride 68 u32)
        #pragma unroll
        for (int f = 0; f < 8; f++) {
            const int jc = jw / 2 + f * 4 + tg;
            float v0 = fmaxf(d[f][0], 0.0f), v1 = fmaxf(d[f][1], 0.0f);
            float v2 = fmaxf(d[f][2], 0.0f), v3 = fmaxf(d[f][3], 0.0f);
            __half h0, h1, h2, h3; float l0, l1, l2, l3;
            splith(v0, h0, l0); splith(v1, h1, l1);
            splith(v2, h2, l2); splith(v3, h3, l3);
            smu[U_H1H + arow * 68 + jc] =
                packh(__half2float(h0), __half2float(h1));
            smu[U_H1L + arow * 68 + jc] = packh(l0, l1);
            smu[U_H1H + (arow + 8) * 68 + jc] =
                packh(__half2float(h2), __half2float(h3));
            smu[U_H1L + (arow + 8) * 68 + jc] = packh(l2, l3);
        }

        // ---- issue next-tile gather LDGs (latency hidden by GEMM2) ----
        float4 c[8];
        if (hasnext) {
            switch (gq) {
                case 0: gissue<0>(xyn, c);  break;
                case 1: gissue<4>(xyn, c);  break;
                case 2: gissue<8>(xyn, c);  break;
                default: gissue<12>(xyn, c); break;
            }
        }

        __syncthreads();   // h1 visible

        // ============ GEMM2: D2 = h1 @ W2 + b2 (8 k16-steps) ============
        #pragma unroll
        for (int f = 0; f < 8; f++) {
            const float2 bv = *reinterpret_cast<const float2*>(
                sm + F_B2 + jw + f * 8 + tg * 2);
            d[f][0] = bv.x; d[f][1] = bv.y;
            d[f][2] = bv.x; d[f][3] = bv.y;
        }
        #pragma unroll 1
        for (int s = 0; s < 8; s++) {
            const int acol = s * 8 + tg;
            uint32_t ah[4], al[4];
            ah[0] = smu[U_H1H + arow * 68 + acol];
            ah[1] = smu[U_H1H + (arow + 8) * 68 + acol];
            ah[2] = smu[U_H1H + arow * 68 + acol + 4];
            ah[3] = smu[U_H1H + (arow + 8) * 68 + acol + 4];
            al[0] = smu[U_H1L + arow * 68 + acol];
            al[1] = smu[U_H1L + (arow + 8) * 68 + acol];
            al[2] = smu[U_H1L + arow * 68 + acol + 4];
            al[3] = smu[U_H1L + (arow + 8) * 68 + acol + 4];
            const int fb = ((s * 16 + ch * 8) * 32 + lane) * 2;
            #pragma unroll
            for (int f = 0; f < 8; f++) {
                const uint2 w = *reinterpret_cast<const uint2*>(
                    smu + U_W2F + fb + f * 64);
                mmah(d[f], ah, w.x, w.y);
                mmah(d[f], al, w.x, w.y);
            }
        }

        // ============ epilogue: relu + (W3/SCALE) dot + reduce ============
        {
            float slo = 0.0f, shi = 0.0f;
            #pragma unroll
            for (int f = 0; f < 8; f++) {
                const int jc = jw + f * 8 + tg * 2;
                const float w3a = sm[F_W3 + jc];
                const float w3b = sm[F_W3 + jc + 1];
                slo = fmaf(fmaxf(d[f][0], 0.0f), w3a, slo);
                slo = fmaf(fmaxf(d[f][1], 0.0f), w3b, slo);
                shi = fmaf(fmaxf(d[f][2], 0.0f), w3a, shi);
                shi = fmaf(fmaxf(d[f][3], 0.0f), w3b, shi);
            }
            slo += __shfl_xor_sync(0xFFFFFFFF, slo, 1);
            slo += __shfl_xor_sync(0xFFFFFFFF, slo, 2);
            shi += __shfl_xor_sync(0xFFFFFFFF, shi, 1);
            shi += __shfl_xor_sync(0xFFFFFFFF, shi, 2);
            if (tg == 0) {
                sm[F_PART + arow * 2 + ch]       = slo;
                sm[F_PART + (arow + 8) * 2 + ch] = shi;
            }
        }
        __syncthreads();   // PART visible

        if (tid < 128)
            out[t * 128 + tid] = sm[F_PART + tid * 2]
                               + sm[F_PART + tid * 2 + 1]
                               + sm[F_B3];

        // ---- finish pipelined gather: lerp + split -> feat[buf^1] ----
        if (hasnext) {
            float f[8];
            switch (gq) {
                case 0: gfinish<0>(xyn, c, f);  break;
                case 1: gfinish<4>(xyn, c, f);  break;
                case 2: gfinish<8>(xyn, c, f);  break;
                default: gfinish<12>(xyn, c, f); break;
            }
            feat_store(smu, U_FEAT + (buf ^ 1) * (2 * FEAT_PL), gpt, gq, f);
        }
        // visibility provided by next iteration's top barrier
    }
}

extern "C" void kernel_launch(void* const* d_in, const int* in_sizes, int n_in,
                              void* d_out, int out_size)
{
    const float* x     = (const float*)d_in[0];
    const float* grids = (const float*)d_in[1];
    const float* W1    = (const float*)d_in[2];
    const float* b1    = (const float*)d_in[3];
    const float* W2    = (const float*)d_in[4];
    const float* b2    = (const float*)d_in[5];
    const float* W3    = (const float*)d_in[6];
    const float* b3    = (const float*)d_in[7];
    float* out = (float*)d_out;
    (void)in_sizes; (void)n_in; (void)out_size;

    cudaFuncSetAttribute(Model_61065845014888_kernel,
                         cudaFuncAttributeMaxDynamicSharedMemorySize, SMEM_BYTES);

    repack_kernel<<<(16 * GC + 255) / 256, 256>>>(grids);
    Model_61065845014888_kernel<<<NCTA, TPB, SMEM_BYTES>>>(
        x, W1, b1, W2, b2, W3, b3, out);
}

// round 16
// speedup vs baseline: 1.7263x; 1.1481x over previous
#include <cuda_runtime.h>
#include <cuda_fp16.h>
#include <cstdint>

// ---------------------------------------------------------------------------
// Instant-NGP MLP via mma.sync m16n8k16 FP16 (f32 accum), 2-term A-split.
// Round 16: grid repacked as fp16 2x2 patches pre-scaled x1024
// (1 LDG.128 per level), weight fragments paired into uint4 (LDS.128).
// Pipelined gather, warp-uniform level groups, static schedule.
// ---------------------------------------------------------------------------

#define NPTS    2097152
#define NTILES  (NPTS / 128)     // 16384
#define TPB     512
#define NCTA    148
#define GS      513
#define GC      (GS * GS)
#define SCALE   1024.0f
#define INVSCALE (1.0f / 1024.0f)

// SMEM map in u32 units (all bases 16B-aligned)
#define U_W1F   0                 // 2048 (fp16 plane, paired-frag uint4)
#define U_W2F   2048              // 8192
#define U_FEAT  10240             // 2 bufs x (H 2560 + L 2560) = 10240
#define FEAT_PL 2560
#define U_H1H   20480             // 128*68 = 8704
#define U_H1L   29184             // 8704
#define F_B1    37888
#define F_B2    38016
#define F_W3    38144
#define F_B3    38272             // 4
#define F_PART  38276             // 256
#define SM_U32  38532
#define SMEM_BYTES (SM_U32 * 4)   // 154128 B

// fp16 2x2-patch grid, pre-scaled x1024:
// P[l][i][j] = (g[i][j], g[i][j+1], g[i+1][j], g[i+1][j+1]) * 1024, 8 halves
__device__ uint4 g_packh[16 * GC];   // 67.4 MB

__device__ constexpr int kResTab[16] = {16, 20, 25, 32, 40, 50, 64, 80,
                                        101, 128, 161, 203, 256, 322, 406, 512};

__device__ __forceinline__ uint32_t packh(float e0, float e1) {
    __half2 t = __floats2half2_rn(e0, e1);
    return *reinterpret_cast<uint32_t*>(&t);
}
__device__ __forceinline__ float2 h2f(uint32_t u) {
    __half2 h = *reinterpret_cast<__half2*>(&u);
    return __half22float2(h);
}
__device__ __forceinline__ void splith(float v, __half& hi, float& lo) {
    hi = __float2half_rn(v);
    lo = v - __half2float(hi);
}

__device__ __forceinline__ void mmah(float* d, const uint32_t* a,
                                     uint32_t b0, uint32_t b1) {
    asm volatile(
        "mma.sync.aligned.m16n8k16.row.col.f32.f16.f16.f32 "
        "{%0,%1,%2,%3}, {%4,%5,%6,%7}, {%8,%9}, {%0,%1,%2,%3};"
        : "+f"(d[0]), "+f"(d[1]), "+f"(d[2]), "+f"(d[3])
        : "r"(a[0]), "r"(a[1]), "r"(a[2]), "r"(a[3]), "r"(b0), "r"(b1));
}

// pinned-issue-point 128-bit global load
__device__ __forceinline__ uint4 ldg4u(const uint4* p) {
    uint4 v;
    asm volatile("ld.global.nc.v4.u32 {%0,%1,%2,%3}, [%4];"
                 : "=r"(v.x), "=r"(v.y), "=r"(v.z), "=r"(v.w) : "l"(p));
    return v;
}

// grid repack: 4 float2 corner reads -> 1 fp16 2x2 patch (x1024)
__global__ __launch_bounds__(256)
void repack_kernel(const float* __restrict__ grids) {
    int idx = blockIdx.x * 256 + threadIdx.x;
    if (idx >= 16 * GC) return;
    int j = idx % GS;
    int i = (idx / GS) % GS;
    int l = idx / GC;
    int j1 = min(j + 1, GS - 1), i1 = min(i + 1, GS - 1);
    const float2* g = reinterpret_cast<const float2*>(grids) + (size_t)l * GC;
    float2 f00 = __ldg(g + i * GS + j);
    float2 f01 = __ldg(g + i * GS + j1);
    float2 f10 = __ldg(g + i1 * GS + j);
    float2 f11 = __ldg(g + i1 * GS + j1);
    g_packh[idx] = make_uint4(
        packh(f00.x * SCALE, f00.y * SCALE),
        packh(f01.x * SCALE, f01.y * SCALE),
        packh(f10.x * SCALE, f10.y * SCALE),
        packh(f11.x * SCALE, f11.y * SCALE));
}

// ---- pipelined gather phases (4 levels, warp-uniform base) ----
template <int L0>
__device__ __forceinline__ void gissue(float2 xy, uint4* c) {
    #pragma unroll
    for (int i = 0; i < 4; i++) {
        const int   ri = kResTab[L0 + i];
        const float rf = (float)ri;
        int ix0 = min(max((int)floorf(xy.x * rf), 0), ri);
        int iy0 = min(max((int)floorf(xy.y * rf), 0), ri);
        c[i] = ldg4u(g_packh + (size_t)(L0 + i) * GC + ix0 * GS + iy0);
    }
}
template <int L0>
__device__ __forceinline__ void gfinish(float2 xy, const uint4* c, float* f) {
    #pragma unroll
    for (int i = 0; i < 4; i++) {
        const float rf = (float)kResTab[L0 + i];
        const float fx = xy.x * rf, fy = xy.y * rf;
        const float wx = fx - floorf(fx), wy = fy - floorf(fy);
        const float owx = 1.0f - wx, owy = 1.0f - wy;
        const float2 f00 = h2f(c[i].x);
        const float2 f01 = h2f(c[i].y);
        const float2 f10 = h2f(c[i].z);
        const float2 f11 = h2f(c[i].w);
        const float t00 = f00.x * owx + f10.x * wx;
        const float t01 = f00.y * owx + f10.y * wx;
        const float t10 = f01.x * owx + f11.x * wx;
        const float t11 = f01.y * owx + f11.y * wx;
        f[2*i+0] = t00 * owy + t10 * wy;    // already SCALE-scaled
        f[2*i+1] = t01 * owy + t11 * wy;
    }
}

// split + store one point's 8 (pre-scaled) features into a feat buffer
__device__ __forceinline__ void feat_store(uint32_t* smu, int bufbase,
                                           int gpt, int gq, const float* f) {
    uint32_t hi[4], lo[4];
    #pragma unroll
    for (int c = 0; c < 4; c++) {
        __half h0, h1; float l0, l1;
        splith(f[2*c],   h0, l0);
        splith(f[2*c+1], h1, l1);
        hi[c] = packh(__half2float(h0), __half2float(h1));
        lo[c] = packh(l0, l1);
    }
    *reinterpret_cast<uint4*>(smu + bufbase + gpt * 20 + gq * 4) =
        make_uint4(hi[0], hi[1], hi[2], hi[3]);
    *reinterpret_cast<uint4*>(smu + bufbase + FEAT_PL + gpt * 20 + gq * 4) =
        make_uint4(lo[0], lo[1], lo[2], lo[3]);
}

__global__ __launch_bounds__(TPB, 1)
void Model_61065845014888_kernel(
    const float* __restrict__ x,
    const float* __restrict__ W1, const float* __restrict__ b1,
    const float* __restrict__ W2, const float* __restrict__ b2,
    const float* __restrict__ W3, const float* __restrict__ b3,
    float* __restrict__ out)
{
    extern __shared__ float sm[];
    uint32_t* smu = reinterpret_cast<uint32_t*>(sm);
    uint4*    sm4 = reinterpret_cast<uint4*>(sm);
    const int tid = threadIdx.x;

    // ---- stage fp16 weights, paired fragments (f, f+1) per uint4, once ----
    // uint4 q: ln = q&31, fp = (q>>5)&7, s = q>>8
    //   g0 = 2*fp, g1 = 2*fp+1 ; k0 = s*16+2*(ln&3), k1 = k0+8 ; j = g*8+(ln>>2)
    //   components: (g0:r0, g0:r1, g1:r0, g1:r1)
    for (int q = tid; q < 512; q += TPB) {       // W1: 2 s * 8 fp * 32 ln
        int ln = q & 31, fp = (q >> 5) & 7, s = q >> 8;
        int k0 = s * 16 + 2 * (ln & 3), k1 = k0 + 8;
        int j0 = (2 * fp) * 8 + (ln >> 2);
        int j1 = j0 + 8;
        sm4[U_W1F / 4 + q] = make_uint4(
            packh(W1[k0 * 128 + j0], W1[(k0 + 1) * 128 + j0]),
            packh(W1[k1 * 128 + j0], W1[(k1 + 1) * 128 + j0]),
            packh(W1[k0 * 128 + j1], W1[(k0 + 1) * 128 + j1]),
            packh(W1[k1 * 128 + j1], W1[(k1 + 1) * 128 + j1]));
    }
    for (int q = tid; q < 2048; q += TPB) {      // W2: 8 s * 8 fp * 32 ln
        int ln = q & 31, fp = (q >> 5) & 7, s = q >> 8;
        int k0 = s * 16 + 2 * (ln & 3), k1 = k0 + 8;
        int j0 = (2 * fp) * 8 + (ln >> 2);
        int j1 = j0 + 8;
        sm4[U_W2F / 4 + q] = make_uint4(
            packh(W2[k0 * 128 + j0], W2[(k0 + 1) * 128 + j0]),
            packh(W2[k1 * 128 + j0], W2[(k1 + 1) * 128 + j0]),
            packh(W2[k0 * 128 + j1], W2[(k0 + 1) * 128 + j1]),
            packh(W2[k1 * 128 + j1], W2[(k1 + 1) * 128 + j1]));
    }
    if (tid < 128) {
        sm[F_B1 + tid] = b1[tid] * SCALE;
        sm[F_B2 + tid] = b2[tid] * SCALE;
        sm[F_W3 + tid] = W3[tid] * INVSCALE;
    }
    if (tid == 0) sm[F_B3] = b3[0];

    const int wid  = tid >> 5;
    const int lane = tid & 31;
    const int rg   = wid & 7;
    const int ch   = wid >> 3;
    const int tg   = lane & 3;
    const int gid  = lane >> 2;
    const int arow = rg * 16 + gid;
    const int jw   = ch * 64;

    const int gq  = wid & 3;                // warp-uniform level group
    const int gpt = (wid >> 2) * 32 + lane; // point 0..127

    // ---- prologue: gather tile blockIdx.x into feat buf 0 ----
    {
        const float2 xy = __ldg(reinterpret_cast<const float2*>(x)
                                + blockIdx.x * 128 + gpt);
        uint4 c[4]; float f[8];
        switch (gq) {
            case 0: gissue<0>(xy, c);  gfinish<0>(xy, c, f);  break;
            case 1: gissue<4>(xy, c);  gfinish<4>(xy, c, f);  break;
            case 2: gissue<8>(xy, c);  gfinish<8>(xy, c, f);  break;
            default: gissue<12>(xy, c); gfinish<12>(xy, c, f); break;
        }
        feat_store(smu, U_FEAT, gpt, gq, f);
    }

    int buf = 0;
    for (int t = blockIdx.x; t < NTILES; t += NCTA, buf ^= 1) {
        const int  tn      = t + NCTA;
        const bool hasnext = tn < NTILES;
        const float2 xyn = __ldg(reinterpret_cast<const float2*>(x)
                                 + (hasnext ? tn : t) * 128 + gpt);

        __syncthreads();   // feat[buf] visible; weights staged (first iter)

        const int fbH = U_FEAT + buf * (2 * FEAT_PL);
        const int fbL = fbH + FEAT_PL;

        float d[8][4];

        // ============ GEMM1: D1 = feat @ W1 + b1 (2 k16-steps) ============
        #pragma unroll
        for (int f = 0; f < 8; f++) {
            const float2 bv = *reinterpret_cast<const float2*>(
                sm + F_B1 + jw + f * 8 + tg * 2);
            d[f][0] = bv.x; d[f][1] = bv.y;
            d[f][2] = bv.x; d[f][3] = bv.y;
        }
        #pragma unroll
        for (int s = 0; s < 2; s++) {
            const int acol = s * 8 + tg;
            uint32_t ah[4], al[4];
            ah[0] = smu[fbH + arow * 20 + acol];
            ah[1] = smu[fbH + (arow + 8) * 20 + acol];
            ah[2] = smu[fbH + arow * 20 + acol + 4];
            ah[3] = smu[fbH + (arow + 8) * 20 + acol + 4];
            al[0] = smu[fbL + arow * 20 + acol];
            al[1] = smu[fbL + (arow + 8) * 20 + acol];
            al[2] = smu[fbL + arow * 20 + acol + 4];
            al[3] = smu[fbL + (arow + 8) * 20 + acol + 4];
            const int qb = U_W1F / 4 + (s * 8 + ch * 4) * 32 + lane;
            #pragma unroll
            for (int fp = 0; fp < 4; fp++) {
                const uint4 w = sm4[qb + fp * 32];
                mmah(d[2*fp],   ah, w.x, w.y);
                mmah(d[2*fp],   al, w.x, w.y);
                mmah(d[2*fp+1], ah, w.z, w.w);
                mmah(d[2*fp+1], al, w.z, w.w);
            }
        }

        // relu + split-store h1 (stride 68 u32)
        #pragma unroll
        for (int f = 0; f < 8; f++) {
            const int jc = jw / 2 + f * 4 + tg;
            float v0 = fmaxf(d[f][0], 0.0f), v1 = fmaxf(d[f][1], 0.0f);
            float v2 = fmaxf(d[f][2], 0.0f), v3 = fmaxf(d[f][3], 0.0f);
            __half h0, h1, h2, h3; float l0, l1, l2, l3;
            splith(v0, h0, l0); splith(v1, h1, l1);
            splith(v2, h2, l2); splith(v3, h3, l3);
            smu[U_H1H + arow * 68 + jc] =
                packh(__half2float(h0), __half2float(h1));
            smu[U_H1L + arow * 68 + jc] = packh(l0, l1);
            smu[U_H1H + (arow + 8) * 68 + jc] =
                packh(__half2float(h2), __half2float(h3));
            smu[U_H1L + (arow + 8) * 68 + jc] = packh(l2, l3);
        }

        // ---- issue next-tile gather LDGs (latency hidden by GEMM2) ----
        uint4 c[4];
        if (hasnext) {
            switch (gq) {
                case 0: gissue<0>(xyn, c);  break;
                case 1: gissue<4>(xyn, c);  break;
                case 2: gissue<8>(xyn, c);  break;
                default: gissue<12>(xyn, c); break;
            }
        }

        __syncthreads();   // h1 visible

        // ============ GEMM2: D2 = h1 @ W2 + b2 (8 k16-steps) ============
        #pragma unroll
        for (int f = 0; f < 8; f++) {
            const float2 bv = *reinterpret_cast<const float2*>(
                sm + F_B2 + jw + f * 8 + tg * 2);
            d[f][0] = bv.x; d[f][1] = bv.y;
            d[f][2] = bv.x; d[f][3] = bv.y;
        }
        #pragma unroll 1
        for (int s = 0; s < 8; s++) {
            const int acol = s * 8 + tg;
            uint32_t ah[4], al[4];
            ah[0] = smu[U_H1H + arow * 68 + acol];
            ah[1] = smu[U_H1H + (arow + 8) * 68 + acol];
            ah[2] = smu[U_H1H + arow * 68 + acol + 4];
            ah[3] = smu[U_H1H + (arow + 8) * 68 + acol + 4];
            al[0] = smu[U_H1L + arow * 68 + acol];
            al[1] = smu[U_H1L + (arow + 8) * 68 + acol];
            al[2] = smu[U_H1L + arow * 68 + acol + 4];
            al[3] = smu[U_H1L + (arow + 8) * 68 + acol + 4];
            const int qb = U_W2F / 4 + (s * 8 + ch * 4) * 32 + lane;
            #pragma unroll
            for (int fp = 0; fp < 4; fp++) {
                const uint4 w = sm4[qb + fp * 32];
                mmah(d[2*fp],   ah, w.x, w.y);
                mmah(d[2*fp],   al, w.x, w.y);
                mmah(d[2*fp+1], ah, w.z, w.w);
                mmah(d[2*fp+1], al, w.z, w.w);
            }
        }

        // ============ epilogue: relu + (W3/SCALE) dot + reduce ============
        {
            float slo = 0.0f, shi = 0.0f;
            #pragma unroll
            for (int f = 0; f < 8; f++) {
                const int jc = jw + f * 8 + tg * 2;
                const float w3a = sm[F_W3 + jc];
                const float w3b = sm[F_W3 + jc + 1];
                slo = fmaf(fmaxf(d[f][0], 0.0f), w3a, slo);
                slo = fmaf(fmaxf(d[f][1], 0.0f), w3b, slo);
                shi = fmaf(fmaxf(d[f][2], 0.0f), w3a, shi);
                shi = fmaf(fmaxf(d[f][3], 0.0f), w3b, shi);
            }
            slo += __shfl_xor_sync(0xFFFFFFFF, slo, 1);
            slo += __shfl_xor_sync(0xFFFFFFFF, slo, 2);
            shi += __shfl_xor_sync(0xFFFFFFFF, shi, 1);
            shi += __shfl_xor_sync(0xFFFFFFFF, shi, 2);
            if (tg == 0) {
                sm[F_PART + arow * 2 + ch]       = slo;
                sm[F_PART + (arow + 8) * 2 + ch] = shi;
            }
        }
        __syncthreads();   // PART visible

        if (tid < 128)
            out[t * 128 + tid] = sm[F_PART + tid * 2]
                               + sm[F_PART + tid * 2 + 1]
                               + sm[F_B3];

        // ---- finish pipelined gather: lerp + split -> feat[buf^1] ----
        if (hasnext) {
            float f[8];
            switch (gq) {
                case 0: gfinish<0>(xyn, c, f);  break;
                case 1: gfinish<4>(xyn, c, f);  break;
                case 2: gfinish<8>(xyn, c, f);  break;
                default: gfinish<12>(xyn, c, f); break;
            }
            feat_store(smu, U_FEAT + (buf ^ 1) * (2 * FEAT_PL), gpt, gq, f);
        }
        // visibility provided by next iteration's top barrier
    }
}

extern "C" void kernel_launch(void* const* d_in, const int* in_sizes, int n_in,
                              void* d_out, int out_size)
{
    const float* x     = (const float*)d_in[0];
    const float* grids = (const float*)d_in[1];
    const float* W1    = (const float*)d_in[2];
    const float* b1    = (const float*)d_in[3];
    const float* W2    = (const float*)d_in[4];
    const float* b2    = (const float*)d_in[5];
    const float* W3    = (const float*)d_in[6];
    const float* b3    = (const float*)d_in[7];
    float* out = (float*)d_out;
    (void)in_sizes; (void)n_in; (void)out_size;

    cudaFuncSetAttribute(Model_61065845014888_kernel,
                         cudaFuncAttributeMaxDynamicSharedMemorySize, SMEM_BYTES);

    repack_kernel<<<(16 * GC + 255) / 256, 256>>>(grids);
    Model_61065845014888_kernel<<<NCTA, TPB, SMEM_BYTES>>>(
        x, W1, b1, W2, b2, W3, b3, out);
}

// round 17
// speedup vs baseline: 2.2298x; 1.2917x over previous
#include <cuda_runtime.h>
#include <cuda_fp16.h>
#include <cstdint>

// ---------------------------------------------------------------------------
// Instant-NGP MLP via mma.sync m16n8k16 FP16 (f32 accum).
// Round 17: GEMM1 2-term A-split (feat hi/lo), GEMM2 single-plane fp16 h1
// stored directly in A-FRAGMENT layout (1 LDS.128 per s-step, 4 STS.128).
// fp16 2x2-patch grid (x1024), paired uint4 weights, pipelined gather.
// ---------------------------------------------------------------------------

#define NPTS    2097152
#define NTILES  (NPTS / 128)     // 16384
#define TPB     512
#define NCTA    148
#define GS      513
#define GC      (GS * GS)
#define SCALE   1024.0f
#define INVSCALE (1.0f / 1024.0f)

// SMEM map in u32 units (all bases 16B-aligned)
#define U_W1F   0                 // 2048 (fp16 plane, paired-frag uint4)
#define U_W2F   2048              // 8192
#define U_FEAT  10240             // 2 bufs x (H 2560 + L 2560) = 10240
#define FEAT_PL 2560
#define U_H1F   20480             // frag-layout h1: 8 rg * 8 s * 32 ln * 4 = 8192
#define F_B1    28672
#define F_B2    28800
#define F_W3    28928
#define F_B3    29056             // 4
#define F_PART  29060             // 256
#define SM_U32  29316
#define SMEM_BYTES (SM_U32 * 4)   // 117264 B

// fp16 2x2-patch grid, pre-scaled x1024
__device__ uint4 g_packh[16 * GC];   // 67.4 MB

__device__ constexpr int kResTab[16] = {16, 20, 25, 32, 40, 50, 64, 80,
                                        101, 128, 161, 203, 256, 322, 406, 512};

__device__ __forceinline__ uint32_t packh(float e0, float e1) {
    __half2 t = __floats2half2_rn(e0, e1);
    return *reinterpret_cast<uint32_t*>(&t);
}
__device__ __forceinline__ float2 h2f(uint32_t u) {
    __half2 h = *reinterpret_cast<__half2*>(&u);
    return __half22float2(h);
}
__device__ __forceinline__ void splith(float v, __half& hi, float& lo) {
    hi = __float2half_rn(v);
    lo = v - __half2float(hi);
}

__device__ __forceinline__ void mmah(float* d, const uint32_t* a,
                                     uint32_t b0, uint32_t b1) {
    asm volatile(
        "mma.sync.aligned.m16n8k16.row.col.f32.f16.f16.f32 "
        "{%0,%1,%2,%3}, {%4,%5,%6,%7}, {%8,%9}, {%0,%1,%2,%3};"
        : "+f"(d[0]), "+f"(d[1]), "+f"(d[2]), "+f"(d[3])
        : "r"(a[0]), "r"(a[1]), "r"(a[2]), "r"(a[3]), "r"(b0), "r"(b1));
}

// pinned-issue-point 128-bit global load
__device__ __forceinline__ uint4 ldg4u(const uint4* p) {
    uint4 v;
    asm volatile("ld.global.nc.v4.u32 {%0,%1,%2,%3}, [%4];"
                 : "=r"(v.x), "=r"(v.y), "=r"(v.z), "=r"(v.w) : "l"(p));
    return v;
}

// grid repack: 4 float2 corner reads -> 1 fp16 2x2 patch (x1024)
__global__ __launch_bounds__(256)
void repack_kernel(const float* __restrict__ grids) {
    int idx = blockIdx.x * 256 + threadIdx.x;
    if (idx >= 16 * GC) return;
    int j = idx % GS;
    int i = (idx / GS) % GS;
    int l = idx / GC;
    int j1 = min(j + 1, GS - 1), i1 = min(i + 1, GS - 1);
    const float2* g = reinterpret_cast<const float2*>(grids) + (size_t)l * GC;
    float2 f00 = __ldg(g + i * GS + j);
    float2 f01 = __ldg(g + i * GS + j1);
    float2 f10 = __ldg(g + i1 * GS + j);
    float2 f11 = __ldg(g + i1 * GS + j1);
    g_packh[idx] = make_uint4(
        packh(f00.x * SCALE, f00.y * SCALE),
        packh(f01.x * SCALE, f01.y * SCALE),
        packh(f10.x * SCALE, f10.y * SCALE),
        packh(f11.x * SCALE, f11.y * SCALE));
}

// ---- pipelined gather phases (4 levels, warp-uniform base) ----
template <int L0>
__device__ __forceinline__ void gissue(float2 xy, uint4* c) {
    #pragma unroll
    for (int i = 0; i < 4; i++) {
        const int   ri = kResTab[L0 + i];
        const float rf = (float)ri;
        int ix0 = min(max((int)floorf(xy.x * rf), 0), ri);
        int iy0 = min(max((int)floorf(xy.y * rf), 0), ri);
        c[i] = ldg4u(g_packh + (size_t)(L0 + i) * GC + ix0 * GS + iy0);
    }
}
template <int L0>
__device__ __forceinline__ void gfinish(float2 xy, const uint4* c, float* f) {
    #pragma unroll
    for (int i = 0; i < 4; i++) {
        const float rf = (float)kResTab[L0 + i];
        const float fx = xy.x * rf, fy = xy.y * rf;
        const float wx = fx - floorf(fx), wy = fy - floorf(fy);
        const float owx = 1.0f - wx, owy = 1.0f - wy;
        const float2 f00 = h2f(c[i].x);
        const float2 f01 = h2f(c[i].y);
        const float2 f10 = h2f(c[i].z);
        const float2 f11 = h2f(c[i].w);
        const float t00 = f00.x * owx + f10.x * wx;
        const float t01 = f00.y * owx + f10.y * wx;
        const float t10 = f01.x * owx + f11.x * wx;
        const float t11 = f01.y * owx + f11.y * wx;
        f[2*i+0] = t00 * owy + t10 * wy;    // already SCALE-scaled
        f[2*i+1] = t01 * owy + t11 * wy;
    }
}

// split + store one point's 8 (pre-scaled) features into a feat buffer
__device__ __forceinline__ void feat_store(uint32_t* smu, int bufbase,
                                           int gpt, int gq, const float* f) {
    uint32_t hi[4], lo[4];
    #pragma unroll
    for (int c = 0; c < 4; c++) {
        __half h0, h1; float l0, l1;
        splith(f[2*c],   h0, l0);
        splith(f[2*c+1], h1, l1);
        hi[c] = packh(__half2float(h0), __half2float(h1));
        lo[c] = packh(l0, l1);
    }
    *reinterpret_cast<uint4*>(smu + bufbase + gpt * 20 + gq * 4) =
        make_uint4(hi[0], hi[1], hi[2], hi[3]);
    *reinterpret_cast<uint4*>(smu + bufbase + FEAT_PL + gpt * 20 + gq * 4) =
        make_uint4(lo[0], lo[1], lo[2], lo[3]);
}

__global__ __launch_bounds__(TPB, 1)
void Model_61065845014888_kernel(
    const float* __restrict__ x,
    const float* __restrict__ W1, const float* __restrict__ b1,
    const float* __restrict__ W2, const float* __restrict__ b2,
    const float* __restrict__ W3, const float* __restrict__ b3,
    float* __restrict__ out)
{
    extern __shared__ float sm[];
    uint32_t* smu = reinterpret_cast<uint32_t*>(sm);
    uint4*    sm4 = reinterpret_cast<uint4*>(sm);
    const int tid = threadIdx.x;

    // ---- stage fp16 weights, paired fragments (j-pair) per uint4, once ----
    for (int q = tid; q < 512; q += TPB) {       // W1: 2 s * 8 fp * 32 ln
        int ln = q & 31, fp = (q >> 5) & 7, s = q >> 8;
        int k0 = s * 16 + 2 * (ln & 3), k1 = k0 + 8;
        int j0 = (2 * fp) * 8 + (ln >> 2);
        int j1 = j0 + 8;
        sm4[U_W1F / 4 + q] = make_uint4(
            packh(W1[k0 * 128 + j0], W1[(k0 + 1) * 128 + j0]),
            packh(W1[k1 * 128 + j0], W1[(k1 + 1) * 128 + j0]),
            packh(W1[k0 * 128 + j1], W1[(k0 + 1) * 128 + j1]),
            packh(W1[k1 * 128 + j1], W1[(k1 + 1) * 128 + j1]));
    }
    for (int q = tid; q < 2048; q += TPB) {      // W2: 8 s * 8 fp * 32 ln
        int ln = q & 31, fp = (q >> 5) & 7, s = q >> 8;
        int k0 = s * 16 + 2 * (ln & 3), k1 = k0 + 8;
        int j0 = (2 * fp) * 8 + (ln >> 2);
        int j1 = j0 + 8;
        sm4[U_W2F / 4 + q] = make_uint4(
            packh(W2[k0 * 128 + j0], W2[(k0 + 1) * 128 + j0]),
            packh(W2[k1 * 128 + j0], W2[(k1 + 1) * 128 + j0]),
            packh(W2[k0 * 128 + j1], W2[(k0 + 1) * 128 + j1]),
            packh(W2[k1 * 128 + j1], W2[(k1 + 1) * 128 + j1]));
    }
    if (tid < 128) {
        sm[F_B1 + tid] = b1[tid] * SCALE;
        sm[F_B2 + tid] = b2[tid] * SCALE;
        sm[F_W3 + tid] = W3[tid] * INVSCALE;
    }
    if (tid == 0) sm[F_B3] = b3[0];

    const int wid  = tid >> 5;
    const int lane = tid & 31;
    const int rg   = wid & 7;
    const int ch   = wid >> 3;
    const int tg   = lane & 3;
    const int gid  = lane >> 2;
    const int arow = rg * 16 + gid;
    const int jw   = ch * 64;

    const int gq  = wid & 3;                // warp-uniform level group
    const int gpt = (wid >> 2) * 32 + lane; // point 0..127

    // ---- prologue: gather tile blockIdx.x into feat buf 0 ----
    {
        const float2 xy = __ldg(reinterpret_cast<const float2*>(x)
                                + blockIdx.x * 128 + gpt);
        uint4 c[4]; float f[8];
        switch (gq) {
            case 0: gissue<0>(xy, c);  gfinish<0>(xy, c, f);  break;
            case 1: gissue<4>(xy, c);  gfinish<4>(xy, c, f);  break;
            case 2: gissue<8>(xy, c);  gfinish<8>(xy, c, f);  break;
            default: gissue<12>(xy, c); gfinish<12>(xy, c, f); break;
        }
        feat_store(smu, U_FEAT, gpt, gq, f);
    }

    int buf = 0;
    for (int t = blockIdx.x; t < NTILES; t += NCTA, buf ^= 1) {
        const int  tn      = t + NCTA;
        const bool hasnext = tn < NTILES;
        const float2 xyn = __ldg(reinterpret_cast<const float2*>(x)
                                 + (hasnext ? tn : t) * 128 + gpt);

        __syncthreads();   // feat[buf] visible; weights staged (first iter)

        const int fbH = U_FEAT + buf * (2 * FEAT_PL);
        const int fbL = fbH + FEAT_PL;

        float d[8][4];

        // ============ GEMM1: D1 = feat @ W1 + b1 (2 k16-steps, 2-term) =====
        #pragma unroll
        for (int f = 0; f < 8; f++) {
            const float2 bv = *reinterpret_cast<const float2*>(
                sm + F_B1 + jw + f * 8 + tg * 2);
            d[f][0] = bv.x; d[f][1] = bv.y;
            d[f][2] = bv.x; d[f][3] = bv.y;
        }
        #pragma unroll
        for (int s = 0; s < 2; s++) {
            const int acol = s * 8 + tg;
            uint32_t ah[4], al[4];
            ah[0] = smu[fbH + arow * 20 + acol];
            ah[1] = smu[fbH + (arow + 8) * 20 + acol];
            ah[2] = smu[fbH + arow * 20 + acol + 4];
            ah[3] = smu[fbH + (arow + 8) * 20 + acol + 4];
            al[0] = smu[fbL + arow * 20 + acol];
            al[1] = smu[fbL + (arow + 8) * 20 + acol];
            al[2] = smu[fbL + arow * 20 + acol + 4];
            al[3] = smu[fbL + (arow + 8) * 20 + acol + 4];
            const int qb = U_W1F / 4 + (s * 8 + ch * 4) * 32 + lane;
            #pragma unroll
            for (int fp = 0; fp < 4; fp++) {
                const uint4 w = sm4[qb + fp * 32];
                mmah(d[2*fp],   ah, w.x, w.y);
                mmah(d[2*fp],   al, w.x, w.y);
                mmah(d[2*fp+1], ah, w.z, w.w);
                mmah(d[2*fp+1], al, w.z, w.w);
            }
        }

        // relu + store h1 in A-FRAGMENT layout (4 STS.128, single fp16 plane)
        // consumer (rg, s): ah = uint4 at (rg*8+s)*32 + lane
        #pragma unroll
        for (int fp = 0; fp < 4; fp++) {
            const int fe = 2 * fp, fo = fe + 1;
            const int s  = ch * 4 + fp;
            sm4[U_H1F / 4 + (rg * 8 + s) * 32 + lane] = make_uint4(
                packh(fmaxf(d[fe][0], 0.0f), fmaxf(d[fe][1], 0.0f)),
                packh(fmaxf(d[fe][2], 0.0f), fmaxf(d[fe][3], 0.0f)),
                packh(fmaxf(d[fo][0], 0.0f), fmaxf(d[fo][1], 0.0f)),
                packh(fmaxf(d[fo][2], 0.0f), fmaxf(d[fo][3], 0.0f)));
        }

        // ---- issue next-tile gather LDGs (latency hidden by GEMM2) ----
        uint4 c[4];
        if (hasnext) {
            switch (gq) {
                case 0: gissue<0>(xyn, c);  break;
                case 1: gissue<4>(xyn, c);  break;
                case 2: gissue<8>(xyn, c);  break;
                default: gissue<12>(xyn, c); break;
            }
        }

        __syncthreads();   // h1 frags visible

        // ============ GEMM2: D2 = h1 @ W2 + b2 (8 k16-steps, 1-term) =======
        #pragma unroll
        for (int f = 0; f < 8; f++) {
            const float2 bv = *reinterpret_cast<const float2*>(
                sm + F_B2 + jw + f * 8 + tg * 2);
            d[f][0] = bv.x; d[f][1] = bv.y;
            d[f][2] = bv.x; d[f][3] = bv.y;
        }
        #pragma unroll 1
        for (int s = 0; s < 8; s++) {
            const uint4 a4 = sm4[U_H1F / 4 + (rg * 8 + s) * 32 + lane];
            uint32_t ah[4] = {a4.x, a4.y, a4.z, a4.w};
            const int qb = U_W2F / 4 + (s * 8 + ch * 4) * 32 + lane;
            #pragma unroll
            for (int fp = 0; fp < 4; fp++) {
                const uint4 w = sm4[qb + fp * 32];
                mmah(d[2*fp],   ah, w.x, w.y);
                mmah(d[2*fp+1], ah, w.z, w.w);
            }
        }

        // ============ epilogue: relu + (W3/SCALE) dot + reduce ============
        {
            float slo = 0.0f, shi = 0.0f;
            #pragma unroll
            for (int f = 0; f < 8; f++) {
                const int jc = jw + f * 8 + tg * 2;
                const float w3a = sm[F_W3 + jc];
                const float w3b = sm[F_W3 + jc + 1];
                slo = fmaf(fmaxf(d[f][0], 0.0f), w3a, slo);
                slo = fmaf(fmaxf(d[f][1], 0.0f), w3b, slo);
                shi = fmaf(fmaxf(d[f][2], 0.0f), w3a, shi);
                shi = fmaf(fmaxf(d[f][3], 0.0f), w3b, shi);
            }
            slo += __shfl_xor_sync(0xFFFFFFFF, slo, 1);
            slo += __shfl_xor_sync(0xFFFFFFFF, slo, 2);
            shi += __shfl_xor_sync(0xFFFFFFFF, shi, 1);
            shi += __shfl_xor_sync(0xFFFFFFFF, shi, 2);
            if (tg == 0) {
                sm[F_PART + arow * 2 + ch]       = slo;
                sm[F_PART + (arow + 8) * 2 + ch] = shi;
            }
        }
        __syncthreads();   // PART visible

        if (tid < 128)
            out[t * 128 + tid] = sm[F_PART + tid * 2]
                               + sm[F_PART + tid * 2 + 1]
                               + sm[F_B3];

        // ---- finish pipelined gather: lerp + split -> feat[buf^1] ----
        if (hasnext) {
            float f[8];
            switch (gq) {
                case 0: gfinish<0>(xyn, c, f);  break;
                case 1: gfinish<4>(xyn, c, f);  break;
                case 2: gfinish<8>(xyn, c, f);  break;
                default: gfinish<12>(xyn, c, f); break;
            }
            feat_store(smu, U_FEAT + (buf ^ 1) * (2 * FEAT_PL), gpt, gq, f);
        }
        // visibility provided by next iteration's top barrier
    }
}

extern "C" void kernel_launch(void* const* d_in, const int* in_sizes, int n_in,
                              void* d_out, int out_size)
{
    const float* x     = (const float*)d_in[0];
    const float* grids = (const float*)d_in[1];
    const float* W1    = (const float*)d_in[2];
    const float* b1    = (const float*)d_in[3];
    const float* W2    = (const float*)d_in[4];
    const float* b2    = (const float*)d_in[5];
    const float* W3    = (const float*)d_in[6];
    const float* b3    = (const float*)d_in[7];
    float* out = (float*)d_out;
    (void)in_sizes; (void)n_in; (void)out_size;

    cudaFuncSetAttribute(Model_61065845014888_kernel,
                         cudaFuncAttributeMaxDynamicSharedMemorySize, SMEM_BYTES);

    repack_kernel<<<(16 * GC + 255) / 256, 256>>>(grids);
    Model_61065845014888_kernel<<<NCTA, TPB, SMEM_BYTES>>>(
        x, W1, b1, W2, b2, W3, b3, out);
}